// round 7
// baseline (speedup 1.0000x reference)
#include <cuda_runtime.h>
#include <cuda_bf16.h>
#include <math.h>
#include <stdint.h>

// Problem constants
#define Bb 2
#define Nn 2048
#define Hh 1024
#define NH 16
#define HD 64
#define SCALE 0.125f
#define Kdim 1024
#define M_TOT (Bb*Nn)   // 4096

// ---------------------------------------------------------------------------
// Scratch (device globals)
// ---------------------------------------------------------------------------
__device__ __align__(128) float  g_WT  [3*Hh*Kdim];        // W^T fp32 staging (reused)
__device__ __align__(128) int8_t g_X8h [M_TOT*Kdim];
__device__ __align__(128) int8_t g_X8l [M_TOT*Kdim];
__device__ __align__(128) float  g_sX  [M_TOT];
__device__ __align__(128) int8_t g_X28h[M_TOT*Kdim];
__device__ __align__(128) int8_t g_X28l[M_TOT*Kdim];
__device__ __align__(128) float  g_sX2 [M_TOT];
__device__ __align__(128) int8_t g_W8h [3*Hh*Kdim];
__device__ __align__(128) int8_t g_W8l [3*Hh*Kdim];
__device__ __align__(128) float  g_sW  [3*Hh];
__device__ __align__(128) int8_t g_Wo8h[Hh*Kdim];
__device__ __align__(128) int8_t g_Wo8l[Hh*Kdim];
__device__ __align__(128) float  g_sWo [Hh];
// Q/K/V bf16 hi/lo, head-major [b,h,n,d]  (attention stays bf16 3-pass)
__device__ __align__(128) __nv_bfloat16 g_Qhi[Bb*NH*Nn*HD];
__device__ __align__(128) __nv_bfloat16 g_Qlo[Bb*NH*Nn*HD];
__device__ __align__(128) __nv_bfloat16 g_Khi[Bb*NH*Nn*HD];
__device__ __align__(128) __nv_bfloat16 g_Klo[Bb*NH*Nn*HD];
__device__ __align__(128) __nv_bfloat16 g_Vhi[Bb*NH*Nn*HD];
__device__ __align__(128) __nv_bfloat16 g_Vlo[Bb*NH*Nn*HD];
__device__ __align__(128) float  g_Attn[M_TOT*Hh];         // attention out fp32
__device__ __align__(128) int8_t g_A8h [M_TOT*Kdim];
__device__ __align__(128) int8_t g_A8l [M_TOT*Kdim];
__device__ __align__(128) float  g_sA  [M_TOT];

// ---------------------------------------------------------------------------
// PTX helpers
// ---------------------------------------------------------------------------
__device__ __forceinline__ uint32_t smem_u32(const void* p) {
    return (uint32_t)__cvta_generic_to_shared(p);
}
__device__ __forceinline__ void cp_async16(uint32_t d, const void* s) {
    asm volatile("cp.async.cg.shared.global [%0], [%1], 16;\n" :: "r"(d), "l"(s) : "memory");
}
__device__ __forceinline__ void cp_commit() { asm volatile("cp.async.commit_group;\n" ::: "memory"); }
__device__ __forceinline__ void cp_wait1()  { asm volatile("cp.async.wait_group 1;\n" ::: "memory"); }
__device__ __forceinline__ void cp_wait2()  { asm volatile("cp.async.wait_group 2;\n" ::: "memory"); }
__device__ __forceinline__ void ldsm_x4(uint32_t& r0, uint32_t& r1, uint32_t& r2, uint32_t& r3, uint32_t a) {
    asm volatile("ldmatrix.sync.aligned.m8n8.x4.shared.b16 {%0,%1,%2,%3}, [%4];"
                 : "=r"(r0), "=r"(r1), "=r"(r2), "=r"(r3) : "r"(a));
}
__device__ __forceinline__ void ldsm_x4_t(uint32_t& r0, uint32_t& r1, uint32_t& r2, uint32_t& r3, uint32_t a) {
    asm volatile("ldmatrix.sync.aligned.m8n8.x4.trans.shared.b16 {%0,%1,%2,%3}, [%4];"
                 : "=r"(r0), "=r"(r1), "=r"(r2), "=r"(r3) : "r"(a));
}
__device__ __forceinline__ void mma_bf16(float c[4], const uint32_t a[4], const uint32_t b[2]) {
    asm volatile("mma.sync.aligned.m16n8k16.row.col.f32.bf16.bf16.f32 "
                 "{%0,%1,%2,%3}, {%4,%5,%6,%7}, {%8,%9}, {%0,%1,%2,%3};"
                 : "+f"(c[0]), "+f"(c[1]), "+f"(c[2]), "+f"(c[3])
                 : "r"(a[0]), "r"(a[1]), "r"(a[2]), "r"(a[3]), "r"(b[0]), "r"(b[1]));
}
__device__ __forceinline__ void mma_i8(int c[4], const uint32_t a[4], const uint32_t b[2]) {
    asm volatile("mma.sync.aligned.m16n8k32.row.col.s32.s8.s8.s32 "
                 "{%0,%1,%2,%3}, {%4,%5,%6,%7}, {%8,%9}, {%0,%1,%2,%3};"
                 : "+r"(c[0]), "+r"(c[1]), "+r"(c[2]), "+r"(c[3])
                 : "r"(a[0]), "r"(a[1]), "r"(a[2]), "r"(a[3]), "r"(b[0]), "r"(b[1]));
}
__device__ __forceinline__ float ex2f(float x) {
    float y; asm("ex2.approx.f32 %0, %1;" : "=f"(y) : "f"(x)); return y;
}
__device__ __forceinline__ uint32_t packbf(float lo, float hi) {
    __nv_bfloat162 v = __halves2bfloat162(__float2bfloat16(lo), __float2bfloat16(hi));
    return *(uint32_t*)&v;
}

// ---------------------------------------------------------------------------
// Preprocessing kernels
// ---------------------------------------------------------------------------
// Transpose fp32: src [1024][C] -> dst [C][1024]
__global__ __launch_bounds__(256) void tconvf_kernel(const float* __restrict__ src,
                                                     float* __restrict__ dst, int C)
{
    __shared__ float tile[32][33];
    int c0 = blockIdx.x * 32, k0 = blockIdx.y * 32;
    int tx = threadIdx.x, ty = threadIdx.y;  // 32x8
#pragma unroll
    for (int i = 0; i < 32; i += 8)
        tile[ty + i][tx] = src[(size_t)(k0 + ty + i) * C + c0 + tx];
    __syncthreads();
#pragma unroll
    for (int i = 0; i < 32; i += 8)
        dst[(size_t)(c0 + ty + i) * 1024 + k0 + tx] = tile[tx][ty + i];
}

// Per-row 2-split int8 quantization: rows of 1024. One warp per row, 8 rows/block.
__global__ __launch_bounds__(256) void rquant_kernel(const float* __restrict__ src,
                                                     int8_t* __restrict__ hi,
                                                     int8_t* __restrict__ lo,
                                                     float* __restrict__ scale)
{
    int w = threadIdx.x >> 5, lane = threadIdx.x & 31;
    int row = blockIdx.x * 8 + w;
    const float4* p = (const float4*)(src + (size_t)row * 1024);
    float4 v[8];
    float mx = 0.f;
#pragma unroll
    for (int i = 0; i < 8; i++) {
        v[i] = p[lane + i * 32];
        mx = fmaxf(mx, fmaxf(fmaxf(fabsf(v[i].x), fabsf(v[i].y)),
                             fmaxf(fabsf(v[i].z), fabsf(v[i].w))));
    }
#pragma unroll
    for (int off = 16; off >= 1; off >>= 1)
        mx = fmaxf(mx, __shfl_xor_sync(0xffffffffu, mx, off));
    float s   = mx * (1.0f / 127.0f);
    float inv = (mx > 0.f) ? 127.0f / mx : 0.f;
    uint32_t* H = (uint32_t*)(hi + (size_t)row * 1024);
    uint32_t* L = (uint32_t*)(lo + (size_t)row * 1024);
#pragma unroll
    for (int i = 0; i < 8; i++) {
        float f[4] = {v[i].x, v[i].y, v[i].z, v[i].w};
        uint32_t hw = 0, lw = 0;
#pragma unroll
        for (int j = 0; j < 4; j++) {
            int q  = (int)rintf(f[j] * inv);
            float r = fmaf(-s, (float)q, f[j]);
            int ql = (int)rintf(r * inv * 128.0f);
            hw |= ((uint32_t)(q  & 0xff)) << (8 * j);
            lw |= ((uint32_t)(ql & 0xff)) << (8 * j);
        }
        H[lane + i * 32] = hw;
        L[lane + i * 32] = lw;
    }
    if (lane == 0) scale[row] = s;
}

// ---------------------------------------------------------------------------
// INT8 IMMA GEMM: C = sA*sB*( Ah*Bh + (Al*Bh + Ah*Bl)/128 )
// tiles 128x64 int8, 3-stage cp.async, 8 warps, warp tile 64x32
// ---------------------------------------------------------------------------
#define IPITCH 80                   // 64B data + 16 pad
#define ITILE (128*IPITCH)          // 10240
#define IBUF (4*ITILE)              // Ah|Al|Bh|Bl = 40960
#define IGEMM_SMEM (3*IBUF)         // 122880
#define NCHI 16                     // 1024/64

__device__ __forceinline__ void load_chunk_i8(const int8_t* Ah, const int8_t* Al,
                                              const int8_t* Bh, const int8_t* Bl,
                                              uint32_t smbuf, int c, int tid)
{
    int row  = tid >> 1;
    int half = tid & 1;
    size_t g = (size_t)row * Kdim + (size_t)c * 64 + half * 32;
    uint32_t s = smbuf + row * IPITCH + half * 32;
    cp_async16(s,                  Ah + g);
    cp_async16(s + 16,             Ah + g + 16);
    cp_async16(s + ITILE,          Al + g);
    cp_async16(s + ITILE + 16,     Al + g + 16);
    cp_async16(s + 2 * ITILE,      Bh + g);
    cp_async16(s + 2 * ITILE + 16, Bh + g + 16);
    cp_async16(s + 3 * ITILE,      Bl + g);
    cp_async16(s + 3 * ITILE + 16, Bl + g + 16);
}

__device__ __forceinline__ void ldA_i8(uint32_t smA, int wm, int lane, int ks, uint32_t a[4][4]) {
    int lrow  = lane & 15;
    int lcolB = (lane >> 4) * 16 + ks * 32;
#pragma unroll
    for (int mt = 0; mt < 4; mt++)
        ldsm_x4(a[mt][0], a[mt][1], a[mt][2], a[mt][3],
                smA + (wm + mt * 16 + lrow) * IPITCH + lcolB);
}
__device__ __forceinline__ void ldB_i8(uint32_t smB, int wn, int lane, int ks, uint32_t b[4][2]) {
    int brow  = ((lane >> 4) & 1) * 8 + (lane & 7);
    int bcolB = ((lane >> 3) & 1) * 16 + ks * 32;
#pragma unroll
    for (int j2 = 0; j2 < 2; j2++) {
        uint32_t r0, r1, r2, r3;
        ldsm_x4(r0, r1, r2, r3, smB + (wn + j2 * 16 + brow) * IPITCH + bcolB);
        b[j2 * 2][0] = r0; b[j2 * 2][1] = r1;
        b[j2 * 2 + 1][0] = r2; b[j2 * 2 + 1][1] = r3;
    }
}

__device__ __forceinline__ void gemm_i8_mainloop(const int8_t* Ah, const int8_t* Al,
                                                 const int8_t* Bh, const int8_t* Bl,
                                                 uint32_t smb, int tid,
                                                 int hh[4][4][4], int xx[4][4][4])
{
    const int wid = tid >> 5, lane = tid & 31;
    const int wm = (wid >> 2) * 64, wn = (wid & 3) * 32;

    load_chunk_i8(Ah, Al, Bh, Bl, smb,        0, tid); cp_commit();
    load_chunk_i8(Ah, Al, Bh, Bl, smb + IBUF, 1, tid); cp_commit();

    int stage = 0, wstage = 2;
    for (int c = 0; c < NCHI; ++c) {
        uint32_t buf = smb + stage * IBUF;
        cp_wait1();
        __syncthreads();

        uint32_t smAh = buf, smAl = buf + ITILE, smBh = buf + 2 * ITILE, smBl = buf + 3 * ITILE;
#pragma unroll
        for (int ks = 0; ks < 2; ks++) {
            uint32_t ah[4][4], al[4][4], bb[4][2];
            ldA_i8(smAh, wm, lane, ks, ah);
            ldB_i8(smBh, wn, lane, ks, bb);
#pragma unroll
            for (int mt = 0; mt < 4; mt++)
#pragma unroll
                for (int nt = 0; nt < 4; nt++) mma_i8(hh[mt][nt], ah[mt], bb[nt]);
            ldA_i8(smAl, wm, lane, ks, al);
#pragma unroll
            for (int mt = 0; mt < 4; mt++)
#pragma unroll
                for (int nt = 0; nt < 4; nt++) mma_i8(xx[mt][nt], al[mt], bb[nt]);
            ldB_i8(smBl, wn, lane, ks, bb);
#pragma unroll
            for (int mt = 0; mt < 4; mt++)
#pragma unroll
                for (int nt = 0; nt < 4; nt++) mma_i8(xx[mt][nt], ah[mt], bb[nt]);
        }
        if (c + 2 < NCHI)
            load_chunk_i8(Ah, Al, Bh, Bl, smb + wstage * IBUF, c + 2, tid);
        cp_commit();
        stage = (stage + 1) % 3; wstage = (wstage + 1) % 3;
    }
}

// ---------------------------------------------------------------------------
// QKV int8 GEMM: epilogue writes bf16 hi/lo head-major [b,h,n,d]
// ---------------------------------------------------------------------------
__global__ __launch_bounds__(256) void qkv_imma_kernel()
{
    extern __shared__ char sm[];
    uint32_t smb = smem_u32(sm);
    int tid = threadIdx.x;
    int z = blockIdx.z;
    int n0 = blockIdx.x * 128;
    int m0 = blockIdx.y * 128;

    const int8_t* Ah = (z == 0 ? g_X8h : g_X28h) + (size_t)m0 * Kdim;
    const int8_t* Al = (z == 0 ? g_X8l : g_X28l) + (size_t)m0 * Kdim;
    const int8_t* Bh = g_W8h + (size_t)(z * Hh + n0) * Kdim;
    const int8_t* Bl = g_W8l + (size_t)(z * Hh + n0) * Kdim;
    const float* sAarr = (z == 0) ? g_sX : g_sX2;

    int hh[4][4][4], xx[4][4][4];
#pragma unroll
    for (int i = 0; i < 4; i++)
#pragma unroll
        for (int j = 0; j < 4; j++)
#pragma unroll
            for (int k = 0; k < 4; k++) { hh[i][j][k] = 0; xx[i][j][k] = 0; }

    gemm_i8_mainloop(Ah, Al, Bh, Bl, smb, tid, hh, xx);

    __nv_bfloat16* dhi = (z == 0) ? g_Qhi : (z == 1) ? g_Khi : g_Vhi;
    __nv_bfloat16* dlo = (z == 0) ? g_Qlo : (z == 1) ? g_Klo : g_Vlo;
    const int wid = tid >> 5, lane = tid & 31;
    const int wm = (wid >> 2) * 64, wn = (wid & 3) * 32;
    const float inv128 = 0.0078125f;
#pragma unroll
    for (int mt = 0; mt < 4; mt++) {
#pragma unroll
        for (int nt = 0; nt < 4; nt++) {
            int col = n0 + wn + nt * 8 + (lane & 3) * 2;
            int h = col >> 6, d = col & 63;
            float sb0 = g_sW[z * 1024 + col];
            float sb1 = g_sW[z * 1024 + col + 1];
#pragma unroll
            for (int half = 0; half < 2; half++) {
                int gm = m0 + wm + mt * 16 + (lane >> 2) + half * 8;
                int b = gm / Nn, n = gm % Nn;
                float sa = sAarr[gm];
                float v0 = sa * sb0 * ((float)hh[mt][nt][half * 2]     + (float)xx[mt][nt][half * 2]     * inv128);
                float v1 = sa * sb1 * ((float)hh[mt][nt][half * 2 + 1] + (float)xx[mt][nt][half * 2 + 1] * inv128);
                float h0 = __bfloat162float(__float2bfloat16(v0));
                float h1 = __bfloat162float(__float2bfloat16(v1));
                size_t idx = ((((size_t)b * NH + h) * Nn) + n) * HD + d;
                *(uint32_t*)(dhi + idx) = packbf(h0, h1);
                *(uint32_t*)(dlo + idx) = packbf(v0 - h0, v1 - h1);
            }
        }
    }
}

// ---------------------------------------------------------------------------
// Output projection int8 GEMM: out = attn @ Wout + bout (fp32 out)
// ---------------------------------------------------------------------------
__global__ __launch_bounds__(256) void proj_imma_kernel(const float* __restrict__ bout,
                                                        float* __restrict__ out)
{
    extern __shared__ char sm[];
    uint32_t smb = smem_u32(sm);
    int tid = threadIdx.x;
    int n0 = blockIdx.x * 128;
    int m0 = blockIdx.y * 128;

    const int8_t* Ah = g_A8h + (size_t)m0 * Kdim;
    const int8_t* Al = g_A8l + (size_t)m0 * Kdim;
    const int8_t* Bh = g_Wo8h + (size_t)n0 * Kdim;
    const int8_t* Bl = g_Wo8l + (size_t)n0 * Kdim;

    int hh[4][4][4], xx[4][4][4];
#pragma unroll
    for (int i = 0; i < 4; i++)
#pragma unroll
        for (int j = 0; j < 4; j++)
#pragma unroll
            for (int k = 0; k < 4; k++) { hh[i][j][k] = 0; xx[i][j][k] = 0; }

    gemm_i8_mainloop(Ah, Al, Bh, Bl, smb, tid, hh, xx);

    const int wid = tid >> 5, lane = tid & 31;
    const int wm = (wid >> 2) * 64, wn = (wid & 3) * 32;
    const float inv128 = 0.0078125f;
#pragma unroll
    for (int mt = 0; mt < 4; mt++) {
#pragma unroll
        for (int nt = 0; nt < 4; nt++) {
            int col = n0 + wn + nt * 8 + (lane & 3) * 2;
            float sb0 = g_sWo[col], sb1 = g_sWo[col + 1];
            float2 bb = *(const float2*)(bout + col);
#pragma unroll
            for (int half = 0; half < 2; half++) {
                int gm = m0 + wm + mt * 16 + (lane >> 2) + half * 8;
                float sa = g_sA[gm];
                float v0 = sa * sb0 * ((float)hh[mt][nt][half * 2]     + (float)xx[mt][nt][half * 2]     * inv128) + bb.x;
                float v1 = sa * sb1 * ((float)hh[mt][nt][half * 2 + 1] + (float)xx[mt][nt][half * 2 + 1] * inv128) + bb.y;
                *(float2*)(out + (size_t)gm * 1024 + col) = make_float2(v0, v1);
            }
        }
    }
}

// ---------------------------------------------------------------------------
// Tensor-core flash attention (bf16 3-pass, as round 5) — epilogue -> fp32
// ---------------------------------------------------------------------------
#define APITCHB 144
#define QT 128
#define KVT 64
#define MATB (64*APITCHB)
#define KVBUF (4*MATB)
#define QBYTES (128*APITCHB)
#define ATTN_SMEM (2*QBYTES + 3*KVBUF)  // 147456

__device__ __forceinline__ void load_kv_tile(const __nv_bfloat16* const mats[4],
                                             uint32_t bufb, int t, int tid)
{
#pragma unroll
    for (int i = 0; i < 8; i++) {
        int e = tid + i * 256;
        int mat = e >> 9;
        int row = (e >> 3) & 63;
        int c   = e & 7;
        cp_async16(bufb + mat * MATB + row * APITCHB + c * 16,
                   mats[mat] + ((size_t)(t * KVT + row)) * HD + c * 8);
    }
}

__global__ __launch_bounds__(256, 1) void attn_mma_kernel()
{
    extern __shared__ char sm[];
    uint32_t smb = smem_u32(sm);
    const uint32_t QHI = smb, QLO = smb + QBYTES;
    const uint32_t KV0 = smb + 2 * QBYTES;

    const int tid = threadIdx.x, lane = tid & 31, wid = tid >> 5;
    const int bh = blockIdx.y, q0 = blockIdx.x * QT;

    const size_t base = (size_t)bh * Nn * HD;
    const __nv_bfloat16* Qh = g_Qhi + base + (size_t)q0 * HD;
    const __nv_bfloat16* Ql = g_Qlo + base + (size_t)q0 * HD;
    const __nv_bfloat16* kvmats[4] = { g_Khi + base, g_Klo + base, g_Vhi + base, g_Vlo + base };

#pragma unroll
    for (int i = 0; i < 8; i++) {
        int e = tid + i * 256;
        int mat = e >> 10;
        int row = (e >> 3) & 127;
        int c   = e & 7;
        const __nv_bfloat16* src = (mat == 0 ? Qh : Ql) + (size_t)row * HD + c * 8;
        cp_async16((mat == 0 ? QHI : QLO) + row * APITCHB + c * 16, src);
    }
    cp_commit();
    load_kv_tile(kvmats, KV0, 0, tid);          cp_commit();
    load_kv_tile(kvmats, KV0 + KVBUF, 1, tid);  cp_commit();

    cp_wait2();
    __syncthreads();

    uint32_t aqh[4][4], aql[4][4];
    {
        int lrow = lane & 15;
        int lcolB = (lane >> 4) * 16;
        uint32_t qrow = (wid * 16 + lrow) * APITCHB + lcolB;
#pragma unroll
        for (int kt = 0; kt < 4; kt++) {
            ldsm_x4(aqh[kt][0], aqh[kt][1], aqh[kt][2], aqh[kt][3], QHI + qrow + kt * 32);
            ldsm_x4(aql[kt][0], aql[kt][1], aql[kt][2], aql[kt][3], QLO + qrow + kt * 32);
        }
    }

    float O[8][4];
#pragma unroll
    for (int i = 0; i < 8; i++)
#pragma unroll
        for (int j = 0; j < 4; j++) O[i][j] = 0.f;
    float m0 = -INFINITY, m1 = -INFINITY, l0 = 0.f, l1 = 0.f;
    const float cc = SCALE * 1.4426950408889634f;

    const int brow = ((lane >> 4) & 1) * 8 + (lane & 7);
    const int bcolB = ((lane >> 3) & 1) * 16;
    const int vrow = lane & 15;
    const int vcolB = ((lane >> 4) & 1) * 16;

    int stage = 0, wstage = 2;
    for (int t = 0; t < Nn / KVT; ++t) {
        uint32_t buf = KV0 + stage * KVBUF;
        cp_wait1();
        __syncthreads();

        uint32_t KHIb = buf, KLOb = buf + MATB, VHIb = buf + 2 * MATB, VLOb = buf + 3 * MATB;

        float S[8][4];
#pragma unroll
        for (int i = 0; i < 8; i++)
#pragma unroll
            for (int j = 0; j < 4; j++) S[i][j] = 0.f;

        uint32_t bk[8][2];
#pragma unroll
        for (int kt = 0; kt < 4; kt++) {
            uint32_t colB = kt * 32 + bcolB;
#pragma unroll
            for (int g = 0; g < 4; g++)
                ldsm_x4(bk[2 * g][0], bk[2 * g][1], bk[2 * g + 1][0], bk[2 * g + 1][1],
                        KHIb + (g * 16 + brow) * APITCHB + colB);
#pragma unroll
            for (int nt = 0; nt < 8; nt++) mma_bf16(S[nt], aqh[kt], bk[nt]);
#pragma unroll
            for (int nt = 0; nt < 8; nt++) mma_bf16(S[nt], aql[kt], bk[nt]);
#pragma unroll
            for (int g = 0; g < 4; g++)
                ldsm_x4(bk[2 * g][0], bk[2 * g][1], bk[2 * g + 1][0], bk[2 * g + 1][1],
                        KLOb + (g * 16 + brow) * APITCHB + colB);
#pragma unroll
            for (int nt = 0; nt < 8; nt++) mma_bf16(S[nt], aqh[kt], bk[nt]);
        }

        float rm0 = -INFINITY, rm1 = -INFINITY;
#pragma unroll
        for (int j = 0; j < 8; j++) {
            rm0 = fmaxf(rm0, fmaxf(S[j][0], S[j][1]));
            rm1 = fmaxf(rm1, fmaxf(S[j][2], S[j][3]));
        }
        rm0 = fmaxf(rm0, __shfl_xor_sync(0xffffffffu, rm0, 1));
        rm0 = fmaxf(rm0, __shfl_xor_sync(0xffffffffu, rm0, 2));
        rm1 = fmaxf(rm1, __shfl_xor_sync(0xffffffffu, rm1, 1));
        rm1 = fmaxf(rm1, __shfl_xor_sync(0xffffffffu, rm1, 2));
        float mn0 = fmaxf(m0, rm0), mn1 = fmaxf(m1, rm1);
        float a0 = ex2f((m0 - mn0) * cc), a1 = ex2f((m1 - mn1) * cc);
        m0 = mn0; m1 = mn1;
        float mc0 = mn0 * cc, mc1 = mn1 * cc;

        uint32_t phi[4][4], plo[4][4];
        float rs0 = 0.f, rs1 = 0.f;
#pragma unroll
        for (int j = 0; j < 8; j++) {
            float p0 = ex2f(fmaf(S[j][0], cc, -mc0));
            float p1 = ex2f(fmaf(S[j][1], cc, -mc0));
            float p2 = ex2f(fmaf(S[j][2], cc, -mc1));
            float p3 = ex2f(fmaf(S[j][3], cc, -mc1));
            rs0 += p0 + p1; rs1 += p2 + p3;
            float h0 = __bfloat162float(__float2bfloat16(p0));
            float h1 = __bfloat162float(__float2bfloat16(p1));
            float h2 = __bfloat162float(__float2bfloat16(p2));
            float h3 = __bfloat162float(__float2bfloat16(p3));
            int kt = j >> 1, hf = (j & 1) * 2;
            phi[kt][hf]     = packbf(h0, h1);
            phi[kt][hf + 1] = packbf(h2, h3);
            plo[kt][hf]     = packbf(p0 - h0, p1 - h1);
            plo[kt][hf + 1] = packbf(p2 - h2, p3 - h3);
        }
        rs0 += __shfl_xor_sync(0xffffffffu, rs0, 1);
        rs0 += __shfl_xor_sync(0xffffffffu, rs0, 2);
        rs1 += __shfl_xor_sync(0xffffffffu, rs1, 1);
        rs1 += __shfl_xor_sync(0xffffffffu, rs1, 2);
        l0 = l0 * a0 + rs0;
        l1 = l1 * a1 + rs1;
#pragma unroll
        for (int dt = 0; dt < 8; dt++) {
            O[dt][0] *= a0; O[dt][1] *= a0; O[dt][2] *= a1; O[dt][3] *= a1;
        }

        uint32_t bv[8][2];
#pragma unroll
        for (int kt = 0; kt < 4; kt++) {
            uint32_t rowB = (kt * 16 + vrow) * APITCHB + vcolB;
#pragma unroll
            for (int g2 = 0; g2 < 4; g2++)
                ldsm_x4_t(bv[2 * g2][0], bv[2 * g2][1], bv[2 * g2 + 1][0], bv[2 * g2 + 1][1],
                          VHIb + rowB + g2 * 32);
#pragma unroll
            for (int dt = 0; dt < 8; dt++) mma_bf16(O[dt], phi[kt], bv[dt]);
#pragma unroll
            for (int dt = 0; dt < 8; dt++) mma_bf16(O[dt], plo[kt], bv[dt]);
#pragma unroll
            for (int g2 = 0; g2 < 4; g2++)
                ldsm_x4_t(bv[2 * g2][0], bv[2 * g2][1], bv[2 * g2 + 1][0], bv[2 * g2 + 1][1],
                          VLOb + rowB + g2 * 32);
#pragma unroll
            for (int dt = 0; dt < 8; dt++) mma_bf16(O[dt], phi[kt], bv[dt]);
        }

        if (t + 2 < Nn / KVT)
            load_kv_tile(kvmats, KV0 + wstage * KVBUF, t + 2, tid);
        cp_commit();
        stage = (stage + 1) % 3; wstage = (wstage + 1) % 3;
    }

    // epilogue: normalize, write fp32 to g_Attn [b*n][h*64+d]
    const int b = bh >> 4, h = bh & 15;
    float il0 = 1.f / l0, il1 = 1.f / l1;
    size_t row0 = (size_t)b * Nn + q0 + wid * 16 + (lane >> 2);
    size_t row1 = row0 + 8;
#pragma unroll
    for (int dt = 0; dt < 8; dt++) {
        int col = h * 64 + dt * 8 + (lane & 3) * 2;
        *(float2*)(g_Attn + row0 * Hh + col) = make_float2(O[dt][0] * il0, O[dt][1] * il0);
        *(float2*)(g_Attn + row1 * Hh + col) = make_float2(O[dt][2] * il1, O[dt][3] * il1);
    }
}

// ---------------------------------------------------------------------------
extern "C" void kernel_launch(void* const* d_in, const int* in_sizes, int n_in,
                              void* d_out, int out_size)
{
    const float* x    = (const float*)d_in[0];
    const float* x2   = (const float*)d_in[1];
    const float* Wqkv = (const float*)d_in[2];
    const float* Wout = (const float*)d_in[3];
    const float* bout = (const float*)d_in[4];
    float* out = (float*)d_out;

    float *wt, *attn, *sx, *sx2, *sw, *swo, *sa;
    int8_t *x8h, *x8l, *x28h, *x28l, *w8h, *w8l, *wo8h, *wo8l, *a8h, *a8l;
    cudaGetSymbolAddress((void**)&wt,   g_WT);
    cudaGetSymbolAddress((void**)&attn, g_Attn);
    cudaGetSymbolAddress((void**)&x8h,  g_X8h);  cudaGetSymbolAddress((void**)&x8l,  g_X8l);
    cudaGetSymbolAddress((void**)&sx,   g_sX);
    cudaGetSymbolAddress((void**)&x28h, g_X28h); cudaGetSymbolAddress((void**)&x28l, g_X28l);
    cudaGetSymbolAddress((void**)&sx2,  g_sX2);
    cudaGetSymbolAddress((void**)&w8h,  g_W8h);  cudaGetSymbolAddress((void**)&w8l,  g_W8l);
    cudaGetSymbolAddress((void**)&sw,   g_sW);
    cudaGetSymbolAddress((void**)&wo8h, g_Wo8h); cudaGetSymbolAddress((void**)&wo8l, g_Wo8l);
    cudaGetSymbolAddress((void**)&swo,  g_sWo);
    cudaGetSymbolAddress((void**)&a8h,  g_A8h);  cudaGetSymbolAddress((void**)&a8l,  g_A8l);
    cudaGetSymbolAddress((void**)&sa,   g_sA);

    // 0) quantize inputs and weights
    rquant_kernel<<<M_TOT / 8, 256>>>(x,  x8h,  x8l,  sx);
    rquant_kernel<<<M_TOT / 8, 256>>>(x2, x28h, x28l, sx2);
    tconvf_kernel<<<dim3(3 * Hh / 32, Kdim / 32), dim3(32, 8)>>>(Wqkv, wt, 3 * Hh);
    rquant_kernel<<<3 * Hh / 8, 256>>>(wt, w8h, w8l, sw);
    tconvf_kernel<<<dim3(Hh / 32, Kdim / 32), dim3(32, 8)>>>(Wout, wt, Hh);
    rquant_kernel<<<Hh / 8, 256>>>(wt, wo8h, wo8l, swo);

    // 1) QKV projections (int8 IMMA)
    cudaFuncSetAttribute(qkv_imma_kernel, cudaFuncAttributeMaxDynamicSharedMemorySize, IGEMM_SMEM);
    qkv_imma_kernel<<<dim3(Hh / 128, M_TOT / 128, 3), 256, IGEMM_SMEM>>>();

    // 2) Tensor-core flash attention (bf16 3-pass)
    cudaFuncSetAttribute(attn_mma_kernel, cudaFuncAttributeMaxDynamicSharedMemorySize, ATTN_SMEM);
    attn_mma_kernel<<<dim3(Nn / QT, Bb * NH), 256, ATTN_SMEM>>>();

    // 3) quantize attention output, then output projection (int8 IMMA)
    rquant_kernel<<<M_TOT / 8, 256>>>(attn, a8h, a8l, sa);
    cudaFuncSetAttribute(proj_imma_kernel, cudaFuncAttributeMaxDynamicSharedMemorySize, IGEMM_SMEM);
    proj_imma_kernel<<<dim3(Hh / 128, M_TOT / 128), 256, IGEMM_SMEM>>>(bout, out);
}

// round 8
// speedup vs baseline: 2.3406x; 2.3406x over previous
#include <cuda_runtime.h>
#include <cuda_bf16.h>
#include <cuda_fp16.h>
#include <math.h>
#include <stdint.h>

// Problem constants
#define Bb 2
#define Nn 2048
#define Hh 1024
#define NH 16
#define HD 64
#define SCALE 0.125f
#define Kdim 1024
#define M_TOT (Bb*Nn)   // 4096

// ---------------------------------------------------------------------------
// Scratch (device globals; no allocations allowed)
// ---------------------------------------------------------------------------
__device__ __align__(128) __nv_bfloat16 g_Xhi [M_TOT*Kdim];
__device__ __align__(128) __nv_bfloat16 g_Xlo [M_TOT*Kdim];
__device__ __align__(128) __nv_bfloat16 g_X2hi[M_TOT*Kdim];
__device__ __align__(128) __nv_bfloat16 g_X2lo[M_TOT*Kdim];
__device__ __align__(128) __nv_bfloat16 g_Wqhi[3*Hh*Kdim];   // Wqkv^T [3072][1024]
__device__ __align__(128) __nv_bfloat16 g_Wqlo[3*Hh*Kdim];
__device__ __align__(128) __nv_bfloat16 g_Wohi[Hh*Kdim];     // Wout^T [1024][1024]
__device__ __align__(128) __nv_bfloat16 g_Wolo[Hh*Kdim];
// Q/K/V single fp16, head-major [b,h,n,d]
__device__ __align__(128) __half g_Qh[Bb*NH*Nn*HD];
__device__ __align__(128) __half g_Kh[Bb*NH*Nn*HD];
__device__ __align__(128) __half g_Vh[Bb*NH*Nn*HD];
// attention out split bf16 (feeds 3-pass bf16 proj)
__device__ __align__(128) __nv_bfloat16 g_Ahi[M_TOT*Hh];
__device__ __align__(128) __nv_bfloat16 g_Alo[M_TOT*Hh];

// ---------------------------------------------------------------------------
// PTX helpers
// ---------------------------------------------------------------------------
__device__ __forceinline__ uint32_t smem_u32(const void* p) {
    return (uint32_t)__cvta_generic_to_shared(p);
}
__device__ __forceinline__ void cp_async16(uint32_t d, const void* s) {
    asm volatile("cp.async.cg.shared.global [%0], [%1], 16;\n" :: "r"(d), "l"(s) : "memory");
}
__device__ __forceinline__ void cp_commit() { asm volatile("cp.async.commit_group;\n" ::: "memory"); }
__device__ __forceinline__ void cp_wait1()  { asm volatile("cp.async.wait_group 1;\n" ::: "memory"); }
__device__ __forceinline__ void cp_wait2()  { asm volatile("cp.async.wait_group 2;\n" ::: "memory"); }
__device__ __forceinline__ void ldsm_x4(uint32_t& r0, uint32_t& r1, uint32_t& r2, uint32_t& r3, uint32_t a) {
    asm volatile("ldmatrix.sync.aligned.m8n8.x4.shared.b16 {%0,%1,%2,%3}, [%4];"
                 : "=r"(r0), "=r"(r1), "=r"(r2), "=r"(r3) : "r"(a));
}
__device__ __forceinline__ void ldsm_x4_t(uint32_t& r0, uint32_t& r1, uint32_t& r2, uint32_t& r3, uint32_t a) {
    asm volatile("ldmatrix.sync.aligned.m8n8.x4.trans.shared.b16 {%0,%1,%2,%3}, [%4];"
                 : "=r"(r0), "=r"(r1), "=r"(r2), "=r"(r3) : "r"(a));
}
__device__ __forceinline__ void mma_bf16(float c[4], const uint32_t a[4], const uint32_t b[2]) {
    asm volatile("mma.sync.aligned.m16n8k16.row.col.f32.bf16.bf16.f32 "
                 "{%0,%1,%2,%3}, {%4,%5,%6,%7}, {%8,%9}, {%0,%1,%2,%3};"
                 : "+f"(c[0]), "+f"(c[1]), "+f"(c[2]), "+f"(c[3])
                 : "r"(a[0]), "r"(a[1]), "r"(a[2]), "r"(a[3]), "r"(b[0]), "r"(b[1]));
}
__device__ __forceinline__ void mma_f16(float c[4], const uint32_t a[4], const uint32_t b[2]) {
    asm volatile("mma.sync.aligned.m16n8k16.row.col.f32.f16.f16.f32 "
                 "{%0,%1,%2,%3}, {%4,%5,%6,%7}, {%8,%9}, {%0,%1,%2,%3};"
                 : "+f"(c[0]), "+f"(c[1]), "+f"(c[2]), "+f"(c[3])
                 : "r"(a[0]), "r"(a[1]), "r"(a[2]), "r"(a[3]), "r"(b[0]), "r"(b[1]));
}
__device__ __forceinline__ float ex2f(float x) {
    float y; asm("ex2.approx.f32 %0, %1;" : "=f"(y) : "f"(x)); return y;
}
__device__ __forceinline__ uint32_t packbf(float lo, float hi) {
    __nv_bfloat162 v = __halves2bfloat162(__float2bfloat16(lo), __float2bfloat16(hi));
    return *(uint32_t*)&v;
}
__device__ __forceinline__ uint32_t packh(float a, float b) {
    __half2 v = __halves2half2(__float2half_rn(a), __float2half_rn(b));
    return *(uint32_t*)&v;
}

// ---------------------------------------------------------------------------
// GEMM tiling (bf16 3-pass, as round 5)
// ---------------------------------------------------------------------------
#define BMt 128
#define BNt 128
#define KCc 32
#define PITCHB 80
#define TILE_BYTES (128*PITCHB)     // 10240
#define BUF_BYTES (4*TILE_BYTES)    // 40960
#define GEMM_SMEM (3*BUF_BYTES)     // 122880

// ---------------------------------------------------------------------------
// fp32 -> bf16 hi/lo split (element-wise)
// ---------------------------------------------------------------------------
__global__ __launch_bounds__(256) void split_kernel(const float* __restrict__ src,
                                                    __nv_bfloat16* __restrict__ hi,
                                                    __nv_bfloat16* __restrict__ lo,
                                                    int n4)
{
    int i = blockIdx.x * blockDim.x + threadIdx.x;
    if (i >= n4) return;
    float4 v = ((const float4*)src)[i];
    __nv_bfloat16 h0 = __float2bfloat16(v.x), h1 = __float2bfloat16(v.y),
                  h2 = __float2bfloat16(v.z), h3 = __float2bfloat16(v.w);
    __nv_bfloat16 l0 = __float2bfloat16(v.x - __bfloat162float(h0));
    __nv_bfloat16 l1 = __float2bfloat16(v.y - __bfloat162float(h1));
    __nv_bfloat16 l2 = __float2bfloat16(v.z - __bfloat162float(h2));
    __nv_bfloat16 l3 = __float2bfloat16(v.w - __bfloat162float(h3));
    __nv_bfloat162* H = (__nv_bfloat162*)(hi + (size_t)i * 4);
    H[0] = __halves2bfloat162(h0, h1); H[1] = __halves2bfloat162(h2, h3);
    __nv_bfloat162* L = (__nv_bfloat162*)(lo + (size_t)i * 4);
    L[0] = __halves2bfloat162(l0, l1); L[1] = __halves2bfloat162(l2, l3);
}

// Transpose + split: src [1024][C] fp32 -> dst [C][1024] bf16 hi/lo
__global__ __launch_bounds__(256) void tsplit_kernel(const float* __restrict__ src,
                                                     __nv_bfloat16* __restrict__ hi,
                                                     __nv_bfloat16* __restrict__ lo,
                                                     int C)
{
    __shared__ float tile[32][33];
    int c0 = blockIdx.x * 32, k0 = blockIdx.y * 32;
    int tx = threadIdx.x, ty = threadIdx.y;  // 32x8
#pragma unroll
    for (int i = 0; i < 32; i += 8)
        tile[ty + i][tx] = src[(size_t)(k0 + ty + i) * C + c0 + tx];
    __syncthreads();
#pragma unroll
    for (int i = 0; i < 32; i += 8) {
        float v = tile[tx][ty + i];
        __nv_bfloat16 h = __float2bfloat16(v);
        __nv_bfloat16 l = __float2bfloat16(v - __bfloat162float(h));
        size_t o = (size_t)(c0 + ty + i) * 1024 + k0 + tx;
        hi[o] = h; lo[o] = l;
    }
}

// ---------------------------------------------------------------------------
// bf16 3-pass HMMA GEMM mainloop (validated round 5)
// ---------------------------------------------------------------------------
__device__ __forceinline__ void load_chunk(const __nv_bfloat16* A0, const __nv_bfloat16* A1,
                                           const __nv_bfloat16* B0, const __nv_bfloat16* B1,
                                           uint32_t smbuf, int c, int tid)
{
    int row  = tid >> 1;
    int half = (tid & 1) * 2;
    size_t g = (size_t)row * Kdim + (size_t)c * KCc + half * 8;
    uint32_t s = smbuf + row * PITCHB + half * 16;
    cp_async16(s,                       A0 + g);
    cp_async16(s + 16,                  A0 + g + 8);
    cp_async16(s + TILE_BYTES,          A1 + g);
    cp_async16(s + TILE_BYTES + 16,     A1 + g + 8);
    cp_async16(s + 2 * TILE_BYTES,      B0 + g);
    cp_async16(s + 2 * TILE_BYTES + 16, B0 + g + 8);
    cp_async16(s + 3 * TILE_BYTES,      B1 + g);
    cp_async16(s + 3 * TILE_BYTES + 16, B1 + g + 8);
}

__device__ __forceinline__ void ldA(uint32_t smA, int wm, int lane, int k0, uint32_t a[4][4]) {
    int lrow = lane & 15;
    int lcol = (lane >> 4) * 8 + k0;
#pragma unroll
    for (int mt = 0; mt < 4; mt++)
        ldsm_x4(a[mt][0], a[mt][1], a[mt][2], a[mt][3],
                smA + (wm + mt * 16 + lrow) * PITCHB + lcol * 2);
}
__device__ __forceinline__ void ldB(uint32_t smB, int wn, int lane, int k0, uint32_t b[4][2]) {
    int brow = ((lane >> 4) & 1) * 8 + (lane & 7);
    int bcol = ((lane >> 3) & 1) * 8 + k0;
#pragma unroll
    for (int j2 = 0; j2 < 2; j2++) {
        uint32_t r0, r1, r2, r3;
        ldsm_x4(r0, r1, r2, r3, smB + (wn + j2 * 16 + brow) * PITCHB + bcol * 2);
        b[j2 * 2][0] = r0; b[j2 * 2][1] = r1;
        b[j2 * 2 + 1][0] = r2; b[j2 * 2 + 1][1] = r3;
    }
}

__device__ __forceinline__ void gemm_mainloop(const __nv_bfloat16* Ahi, const __nv_bfloat16* Alo,
                                              const __nv_bfloat16* Bhi, const __nv_bfloat16* Blo,
                                              uint32_t smb, int tid, float acc[4][4][4])
{
    const int wid = tid >> 5, lane = tid & 31;
    const int wm = (wid >> 2) * 64, wn = (wid & 3) * 32;
    const int NCH = Kdim / KCc;  // 32

    load_chunk(Ahi, Alo, Bhi, Blo, smb,             0, tid); cp_commit();
    load_chunk(Ahi, Alo, Bhi, Blo, smb + BUF_BYTES, 1, tid); cp_commit();

    int stage = 0, wstage = 2;
    for (int c = 0; c < NCH; ++c) {
        uint32_t buf = smb + stage * BUF_BYTES;
        cp_wait1();
        __syncthreads();

        uint32_t smA_hi = buf, smA_lo = buf + TILE_BYTES;
        uint32_t smB_hi = buf + 2 * TILE_BYTES, smB_lo = buf + 3 * TILE_BYTES;
#pragma unroll
        for (int ks = 0; ks < 2; ks++) {
            int k0 = ks * 16;
            uint32_t ah[4][4], al[4][4], bb[4][2];
            ldA(smA_hi, wm, lane, k0, ah);
            ldB(smB_hi, wn, lane, k0, bb);
#pragma unroll
            for (int mt = 0; mt < 4; mt++)
#pragma unroll
                for (int nt = 0; nt < 4; nt++) mma_bf16(acc[mt][nt], ah[mt], bb[nt]);
            ldA(smA_lo, wm, lane, k0, al);
#pragma unroll
            for (int mt = 0; mt < 4; mt++)
#pragma unroll
                for (int nt = 0; nt < 4; nt++) mma_bf16(acc[mt][nt], al[mt], bb[nt]);
            ldB(smB_lo, wn, lane, k0, bb);
#pragma unroll
            for (int mt = 0; mt < 4; mt++)
#pragma unroll
                for (int nt = 0; nt < 4; nt++) mma_bf16(acc[mt][nt], ah[mt], bb[nt]);
        }
        if (c + 2 < NCH)
            load_chunk(Ahi, Alo, Bhi, Blo, smb + wstage * BUF_BYTES, c + 2, tid);
        cp_commit();
        stage = (stage + 1) % 3; wstage = (wstage + 1) % 3;
    }
}

// ---------------------------------------------------------------------------
// QKV GEMM (bf16 3-pass): epilogue writes single fp16 head-major [b,h,n,d]
// ---------------------------------------------------------------------------
__global__ __launch_bounds__(256) void qkv_mma_kernel()
{
    extern __shared__ char sm[];
    uint32_t smb = smem_u32(sm);
    int tid = threadIdx.x;
    int z = blockIdx.z;
    int n0 = blockIdx.x * BNt;
    int m0 = blockIdx.y * BMt;

    const __nv_bfloat16* Ahi = (z == 0 ? g_Xhi : g_X2hi) + (size_t)m0 * Kdim;
    const __nv_bfloat16* Alo = (z == 0 ? g_Xlo : g_X2lo) + (size_t)m0 * Kdim;
    const __nv_bfloat16* Bhi = g_Wqhi + (size_t)(z * Hh + n0) * Kdim;
    const __nv_bfloat16* Blo = g_Wqlo + (size_t)(z * Hh + n0) * Kdim;

    float acc[4][4][4];
#pragma unroll
    for (int i = 0; i < 4; i++)
#pragma unroll
        for (int j = 0; j < 4; j++)
#pragma unroll
            for (int k = 0; k < 4; k++) acc[i][j][k] = 0.f;

    gemm_mainloop(Ahi, Alo, Bhi, Blo, smb, tid, acc);

    __half* dst = (z == 0) ? g_Qh : (z == 1) ? g_Kh : g_Vh;
    const int wid = tid >> 5, lane = tid & 31;
    const int wm = (wid >> 2) * 64, wn = (wid & 3) * 32;
#pragma unroll
    for (int mt = 0; mt < 4; mt++) {
#pragma unroll
        for (int nt = 0; nt < 4; nt++) {
            int col = n0 + wn + nt * 8 + (lane & 3) * 2;
            int h = col >> 6, d = col & 63;
#pragma unroll
            for (int half = 0; half < 2; half++) {
                int gm = m0 + wm + mt * 16 + (lane >> 2) + half * 8;
                int b = gm / Nn, n = gm % Nn;
                size_t idx = ((((size_t)b * NH + h) * Nn) + n) * HD + d;
                *(uint32_t*)(dst + idx) = packh(acc[mt][nt][half * 2],
                                                acc[mt][nt][half * 2 + 1]);
            }
        }
    }
}

// ---------------------------------------------------------------------------
// Output projection GEMM (bf16 3-pass): out = attn @ Wout + bout
// ---------------------------------------------------------------------------
__global__ __launch_bounds__(256) void proj_mma_kernel(const float* __restrict__ bout,
                                                       float* __restrict__ out)
{
    extern __shared__ char sm[];
    uint32_t smb = smem_u32(sm);
    int tid = threadIdx.x;
    int n0 = blockIdx.x * BNt;
    int m0 = blockIdx.y * BMt;

    const __nv_bfloat16* Ahi = g_Ahi + (size_t)m0 * Kdim;
    const __nv_bfloat16* Alo = g_Alo + (size_t)m0 * Kdim;
    const __nv_bfloat16* Bhi = g_Wohi + (size_t)n0 * Kdim;
    const __nv_bfloat16* Blo = g_Wolo + (size_t)n0 * Kdim;

    float acc[4][4][4];
#pragma unroll
    for (int i = 0; i < 4; i++)
#pragma unroll
        for (int j = 0; j < 4; j++)
#pragma unroll
            for (int k = 0; k < 4; k++) acc[i][j][k] = 0.f;

    gemm_mainloop(Ahi, Alo, Bhi, Blo, smb, tid, acc);

    const int wid = tid >> 5, lane = tid & 31;
    const int wm = (wid >> 2) * 64, wn = (wid & 3) * 32;
#pragma unroll
    for (int mt = 0; mt < 4; mt++) {
#pragma unroll
        for (int nt = 0; nt < 4; nt++) {
            int col = n0 + wn + nt * 8 + (lane & 3) * 2;
            float2 bb = *(const float2*)(bout + col);
#pragma unroll
            for (int half = 0; half < 2; half++) {
                int gm = m0 + wm + mt * 16 + (lane >> 2) + half * 8;
                float2 o = make_float2(acc[mt][nt][half * 2] + bb.x,
                                       acc[mt][nt][half * 2 + 1] + bb.y);
                *(float2*)(out + (size_t)gm * 1024 + col) = o;
            }
        }
    }
}

// ---------------------------------------------------------------------------
// Tensor-core flash attention — single-pass fp16 (Q, K, V, P all fp16)
// ---------------------------------------------------------------------------
#define APITCHB 144
#define QT 128
#define KVT 64
#define MATB (64*APITCHB)              // 9216 per kv matrix
#define KVBUF (2*MATB)                 // K|V = 18432
#define QBYTES (128*APITCHB)           // 18432 (Q single)
#define ATTN_SMEM (QBYTES + 3*KVBUF)   // 73728

__device__ __forceinline__ void load_kv_tile(const __half* K, const __half* V,
                                             uint32_t bufb, int t, int tid)
{
#pragma unroll
    for (int i = 0; i < 4; i++) {
        int e = tid + i * 256;
        int mat = e >> 9;            // 0 = K, 1 = V
        int row = (e >> 3) & 63;
        int c   = e & 7;
        const __half* src = (mat == 0 ? K : V) + ((size_t)(t * KVT + row)) * HD + c * 8;
        cp_async16(bufb + mat * MATB + row * APITCHB + c * 16, src);
    }
}

__global__ __launch_bounds__(256) void attn_mma_kernel()
{
    extern __shared__ char sm[];
    uint32_t smb = smem_u32(sm);
    const uint32_t QS  = smb;
    const uint32_t KV0 = smb + QBYTES;

    const int tid = threadIdx.x, lane = tid & 31, wid = tid >> 5;
    const int bh = blockIdx.y, q0 = blockIdx.x * QT;

    const size_t base = (size_t)bh * Nn * HD;
    const __half* Qp = g_Qh + base + (size_t)q0 * HD;
    const __half* Kp = g_Kh + base;
    const __half* Vp = g_Vh + base;

    // Load Q: 128 rows x 8 chunks = 1024 -> 4/thread
#pragma unroll
    for (int i = 0; i < 4; i++) {
        int e = tid + i * 256;
        int row = e >> 3;
        int c   = e & 7;
        cp_async16(QS + row * APITCHB + c * 16, Qp + (size_t)row * HD + c * 8);
    }
    cp_commit();
    load_kv_tile(Kp, Vp, KV0, 0, tid);          cp_commit();
    load_kv_tile(Kp, Vp, KV0 + KVBUF, 1, tid);  cp_commit();

    cp_wait2();   // Q ready
    __syncthreads();

    // Q fragments (once)
    uint32_t aq[4][4];
    {
        int lrow = lane & 15;
        int lcolB = (lane >> 4) * 16;
        uint32_t qrow = (wid * 16 + lrow) * APITCHB + lcolB;
#pragma unroll
        for (int kt = 0; kt < 4; kt++)
            ldsm_x4(aq[kt][0], aq[kt][1], aq[kt][2], aq[kt][3], QS + qrow + kt * 32);
    }

    float O[8][4];
#pragma unroll
    for (int i = 0; i < 8; i++)
#pragma unroll
        for (int j = 0; j < 4; j++) O[i][j] = 0.f;
    float m0 = -INFINITY, m1 = -INFINITY, l0 = 0.f, l1 = 0.f;
    const float cc = SCALE * 1.4426950408889634f;

    const int brow = ((lane >> 4) & 1) * 8 + (lane & 7);
    const int bcolB = ((lane >> 3) & 1) * 16;
    const int vrow = lane & 15;
    const int vcolB = ((lane >> 4) & 1) * 16;

    int stage = 0, wstage = 2;
    for (int t = 0; t < Nn / KVT; ++t) {
        uint32_t buf = KV0 + stage * KVBUF;
        cp_wait1();
        __syncthreads();

        uint32_t Kb = buf, Vb = buf + MATB;

        // ---- S = Q K^T (single fp16 pass) ----
        float S[8][4];
#pragma unroll
        for (int i = 0; i < 8; i++)
#pragma unroll
            for (int j = 0; j < 4; j++) S[i][j] = 0.f;

        uint32_t bk[8][2];
#pragma unroll
        for (int kt = 0; kt < 4; kt++) {
            uint32_t colB = kt * 32 + bcolB;
#pragma unroll
            for (int g = 0; g < 4; g++)
                ldsm_x4(bk[2 * g][0], bk[2 * g][1], bk[2 * g + 1][0], bk[2 * g + 1][1],
                        Kb + (g * 16 + brow) * APITCHB + colB);
#pragma unroll
            for (int nt = 0; nt < 8; nt++) mma_f16(S[nt], aq[kt], bk[nt]);
        }

        // ---- online softmax (rows r0 = lane>>2, r1 = r0+8) ----
        float rm0 = -INFINITY, rm1 = -INFINITY;
#pragma unroll
        for (int j = 0; j < 8; j++) {
            rm0 = fmaxf(rm0, fmaxf(S[j][0], S[j][1]));
            rm1 = fmaxf(rm1, fmaxf(S[j][2], S[j][3]));
        }
        rm0 = fmaxf(rm0, __shfl_xor_sync(0xffffffffu, rm0, 1));
        rm0 = fmaxf(rm0, __shfl_xor_sync(0xffffffffu, rm0, 2));
        rm1 = fmaxf(rm1, __shfl_xor_sync(0xffffffffu, rm1, 1));
        rm1 = fmaxf(rm1, __shfl_xor_sync(0xffffffffu, rm1, 2));
        float mn0 = fmaxf(m0, rm0), mn1 = fmaxf(m1, rm1);
        float a0 = ex2f((m0 - mn0) * cc), a1 = ex2f((m1 - mn1) * cc);
        m0 = mn0; m1 = mn1;
        float mc0 = mn0 * cc, mc1 = mn1 * cc;

        uint32_t ph[4][4];
        float rs0 = 0.f, rs1 = 0.f;
#pragma unroll
        for (int j = 0; j < 8; j++) {
            float p0 = ex2f(fmaf(S[j][0], cc, -mc0));
            float p1 = ex2f(fmaf(S[j][1], cc, -mc0));
            float p2 = ex2f(fmaf(S[j][2], cc, -mc1));
            float p3 = ex2f(fmaf(S[j][3], cc, -mc1));
            rs0 += p0 + p1; rs1 += p2 + p3;
            int kt = j >> 1, hf = (j & 1) * 2;
            ph[kt][hf]     = packh(p0, p1);
            ph[kt][hf + 1] = packh(p2, p3);
        }
        rs0 += __shfl_xor_sync(0xffffffffu, rs0, 1);
        rs0 += __shfl_xor_sync(0xffffffffu, rs0, 2);
        rs1 += __shfl_xor_sync(0xffffffffu, rs1, 1);
        rs1 += __shfl_xor_sync(0xffffffffu, rs1, 2);
        l0 = l0 * a0 + rs0;
        l1 = l1 * a1 + rs1;
#pragma unroll
        for (int dt = 0; dt < 8; dt++) {
            O[dt][0] *= a0; O[dt][1] *= a0; O[dt][2] *= a1; O[dt][3] *= a1;
        }

        // ---- O += P V (single fp16 pass) ----
        uint32_t bv[8][2];
#pragma unroll
        for (int kt = 0; kt < 4; kt++) {
            uint32_t rowB = (kt * 16 + vrow) * APITCHB + vcolB;
#pragma unroll
            for (int g2 = 0; g2 < 4; g2++)
                ldsm_x4_t(bv[2 * g2][0], bv[2 * g2][1], bv[2 * g2 + 1][0], bv[2 * g2 + 1][1],
                          Vb + rowB + g2 * 32);
#pragma unroll
            for (int dt = 0; dt < 8; dt++) mma_f16(O[dt], ph[kt], bv[dt]);
        }

        if (t + 2 < Nn / KVT)
            load_kv_tile(Kp, Vp, KV0 + wstage * KVBUF, t + 2, tid);
        cp_commit();
        stage = (stage + 1) % 3; wstage = (wstage + 1) % 3;
    }

    // ---- epilogue: normalize, write bf16 hi/lo to g_Ahi/g_Alo [b*n][h*64+d] ----
    const int b = bh >> 4, h = bh & 15;
    float il0 = 1.f / l0, il1 = 1.f / l1;
    size_t row0 = (size_t)b * Nn + q0 + wid * 16 + (lane >> 2);
    size_t row1 = row0 + 8;
#pragma unroll
    for (int dt = 0; dt < 8; dt++) {
        int col = h * 64 + dt * 8 + (lane & 3) * 2;
        float v0 = O[dt][0] * il0, v1 = O[dt][1] * il0;
        float v2 = O[dt][2] * il1, v3 = O[dt][3] * il1;
        float h0 = __bfloat162float(__float2bfloat16(v0));
        float h1 = __bfloat162float(__float2bfloat16(v1));
        float h2 = __bfloat162float(__float2bfloat16(v2));
        float h3 = __bfloat162float(__float2bfloat16(v3));
        *(uint32_t*)(g_Ahi + row0 * Hh + col) = packbf(h0, h1);
        *(uint32_t*)(g_Alo + row0 * Hh + col) = packbf(v0 - h0, v1 - h1);
        *(uint32_t*)(g_Ahi + row1 * Hh + col) = packbf(h2, h3);
        *(uint32_t*)(g_Alo + row1 * Hh + col) = packbf(v2 - h2, v3 - h3);
    }
}

// ---------------------------------------------------------------------------
extern "C" void kernel_launch(void* const* d_in, const int* in_sizes, int n_in,
                              void* d_out, int out_size)
{
    const float* x    = (const float*)d_in[0];
    const float* x2   = (const float*)d_in[1];
    const float* Wqkv = (const float*)d_in[2];
    const float* Wout = (const float*)d_in[3];
    const float* bout = (const float*)d_in[4];
    float* out = (float*)d_out;

    // 0) fp32 -> bf16 hi/lo splits (+ weight transposes)
    {
        __nv_bfloat16 *xh, *xl, *x2h, *x2l, *wqh, *wql, *woh, *wol;
        cudaGetSymbolAddress((void**)&xh,  g_Xhi);  cudaGetSymbolAddress((void**)&xl,  g_Xlo);
        cudaGetSymbolAddress((void**)&x2h, g_X2hi); cudaGetSymbolAddress((void**)&x2l, g_X2lo);
        cudaGetSymbolAddress((void**)&wqh, g_Wqhi); cudaGetSymbolAddress((void**)&wql, g_Wqlo);
        cudaGetSymbolAddress((void**)&woh, g_Wohi); cudaGetSymbolAddress((void**)&wol, g_Wolo);

        int n4 = M_TOT * Kdim / 4;
        split_kernel<<<(n4 + 255) / 256, 256>>>(x,  xh,  xl,  n4);
        split_kernel<<<(n4 + 255) / 256, 256>>>(x2, x2h, x2l, n4);
        tsplit_kernel<<<dim3(3 * Hh / 32, Kdim / 32), dim3(32, 8)>>>(Wqkv, wqh, wql, 3 * Hh);
        tsplit_kernel<<<dim3(Hh / 32,     Kdim / 32), dim3(32, 8)>>>(Wout, woh, wol, Hh);
    }

    // 1) QKV projections (bf16 3-pass HMMA)
    cudaFuncSetAttribute(qkv_mma_kernel, cudaFuncAttributeMaxDynamicSharedMemorySize, GEMM_SMEM);
    qkv_mma_kernel<<<dim3(Hh / BNt, M_TOT / BMt, 3), 256, GEMM_SMEM>>>();

    // 2) Tensor-core flash attention (single-pass fp16)
    cudaFuncSetAttribute(attn_mma_kernel, cudaFuncAttributeMaxDynamicSharedMemorySize, ATTN_SMEM);
    attn_mma_kernel<<<dim3(Nn / QT, Bb * NH), 256, ATTN_SMEM>>>();

    // 3) Output projection (bf16 3-pass HMMA)
    cudaFuncSetAttribute(proj_mma_kernel, cudaFuncAttributeMaxDynamicSharedMemorySize, GEMM_SMEM);
    proj_mma_kernel<<<dim3(Hh / BNt, M_TOT / BMt), 256, GEMM_SMEM>>>(bout, out);
}

// round 9
// speedup vs baseline: 4.1908x; 1.7904x over previous
#include <cuda_runtime.h>
#include <cuda_fp16.h>
#include <math.h>
#include <stdint.h>

// Problem constants
#define Bb 2
#define Nn 2048
#define Hh 1024
#define NH 16
#define HD 64
#define SCALE 0.125f
#define Kdim 1024
#define M_TOT (Bb*Nn)   // 4096

// ---------------------------------------------------------------------------
// Scratch (device globals; no allocations allowed)
// ---------------------------------------------------------------------------
__device__ __align__(128) __half g_X  [M_TOT*Kdim];     // x fp16
__device__ __align__(128) __half g_X2 [M_TOT*Kdim];     // x2 fp16
__device__ __align__(128) __half g_Wq [3*Hh*Kdim];      // Wqkv^T [3072][1024] fp16
__device__ __align__(128) __half g_Wo [Hh*Kdim];        // Wout^T fp16
// Q/K/V single fp16, head-major [b,h,n,d]
__device__ __align__(128) __half g_Qh[Bb*NH*Nn*HD];
__device__ __align__(128) __half g_Kh[Bb*NH*Nn*HD];
__device__ __align__(128) __half g_Vh[Bb*NH*Nn*HD];
// attention out single fp16 [b*n][h*d]
__device__ __align__(128) __half g_Ah[M_TOT*Hh];

// ---------------------------------------------------------------------------
// PTX helpers
// ---------------------------------------------------------------------------
__device__ __forceinline__ uint32_t smem_u32(const void* p) {
    return (uint32_t)__cvta_generic_to_shared(p);
}
__device__ __forceinline__ void cp_async16(uint32_t d, const void* s) {
    asm volatile("cp.async.cg.shared.global [%0], [%1], 16;\n" :: "r"(d), "l"(s) : "memory");
}
__device__ __forceinline__ void cp_commit() { asm volatile("cp.async.commit_group;\n" ::: "memory"); }
__device__ __forceinline__ void cp_wait1()  { asm volatile("cp.async.wait_group 1;\n" ::: "memory"); }
__device__ __forceinline__ void cp_wait2()  { asm volatile("cp.async.wait_group 2;\n" ::: "memory"); }
__device__ __forceinline__ void ldsm_x4(uint32_t& r0, uint32_t& r1, uint32_t& r2, uint32_t& r3, uint32_t a) {
    asm volatile("ldmatrix.sync.aligned.m8n8.x4.shared.b16 {%0,%1,%2,%3}, [%4];"
                 : "=r"(r0), "=r"(r1), "=r"(r2), "=r"(r3) : "r"(a));
}
__device__ __forceinline__ void ldsm_x4_t(uint32_t& r0, uint32_t& r1, uint32_t& r2, uint32_t& r3, uint32_t a) {
    asm volatile("ldmatrix.sync.aligned.m8n8.x4.trans.shared.b16 {%0,%1,%2,%3}, [%4];"
                 : "=r"(r0), "=r"(r1), "=r"(r2), "=r"(r3) : "r"(a));
}
__device__ __forceinline__ void mma_f16(float c[4], const uint32_t a[4], const uint32_t b[2]) {
    asm volatile("mma.sync.aligned.m16n8k16.row.col.f32.f16.f16.f32 "
                 "{%0,%1,%2,%3}, {%4,%5,%6,%7}, {%8,%9}, {%0,%1,%2,%3};"
                 : "+f"(c[0]), "+f"(c[1]), "+f"(c[2]), "+f"(c[3])
                 : "r"(a[0]), "r"(a[1]), "r"(a[2]), "r"(a[3]), "r"(b[0]), "r"(b[1]));
}
__device__ __forceinline__ float ex2f(float x) {
    float y; asm("ex2.approx.f32 %0, %1;" : "=f"(y) : "f"(x)); return y;
}
__device__ __forceinline__ uint32_t packh(float a, float b) {
    __half2 v = __halves2half2(__float2half_rn(a), __float2half_rn(b));
    return *(uint32_t*)&v;
}

// ---------------------------------------------------------------------------
// GEMM tiling: single fp16 A and B -> 2 tiles per chunk
// ---------------------------------------------------------------------------
#define BMt 128
#define BNt 128
#define KCc 32
#define PITCHB 80
#define TILE_BYTES (128*PITCHB)     // 10240
#define BUF_BYTES (2*TILE_BYTES)    // A|B = 20480
#define GEMM_SMEM (3*BUF_BYTES)     // 61440

// ---------------------------------------------------------------------------
// fp32 -> fp16 convert (element-wise)
// ---------------------------------------------------------------------------
__global__ __launch_bounds__(256) void conv_kernel(const float* __restrict__ src,
                                                   __half* __restrict__ dst, int n4)
{
    int i = blockIdx.x * blockDim.x + threadIdx.x;
    if (i >= n4) return;
    float4 v = ((const float4*)src)[i];
    __half2* D = (__half2*)(dst + (size_t)i * 4);
    D[0] = __halves2half2(__float2half_rn(v.x), __float2half_rn(v.y));
    D[1] = __halves2half2(__float2half_rn(v.z), __float2half_rn(v.w));
}

// Transpose + convert: src [1024][C] fp32 -> dst [C][1024] fp16
__global__ __launch_bounds__(256) void tconv_kernel(const float* __restrict__ src,
                                                    __half* __restrict__ dst, int C)
{
    __shared__ float tile[32][33];
    int c0 = blockIdx.x * 32, k0 = blockIdx.y * 32;
    int tx = threadIdx.x, ty = threadIdx.y;  // 32x8
#pragma unroll
    for (int i = 0; i < 32; i += 8)
        tile[ty + i][tx] = src[(size_t)(k0 + ty + i) * C + c0 + tx];
    __syncthreads();
#pragma unroll
    for (int i = 0; i < 32; i += 8)
        dst[(size_t)(c0 + ty + i) * 1024 + k0 + tx] = __float2half_rn(tile[tx][ty + i]);
}

// ---------------------------------------------------------------------------
// fp16 single-pass HMMA GEMM mainloop: C[128,128] = A @ B^T, K=1024
// 3-stage cp.async pipeline, one __syncthreads per chunk.
// ---------------------------------------------------------------------------
__device__ __forceinline__ void load_chunk(const __half* A, const __half* B,
                                           uint32_t smbuf, int c, int tid)
{
    int row  = tid >> 1;
    int half = (tid & 1) * 2;
    size_t g = (size_t)row * Kdim + (size_t)c * KCc + half * 8;
    uint32_t s = smbuf + row * PITCHB + half * 16;
    cp_async16(s,                   A + g);
    cp_async16(s + 16,              A + g + 8);
    cp_async16(s + TILE_BYTES,      B + g);
    cp_async16(s + TILE_BYTES + 16, B + g + 8);
}

__device__ __forceinline__ void ldA(uint32_t smA, int wm, int lane, int k0, uint32_t a[4][4]) {
    int lrow = lane & 15;
    int lcol = (lane >> 4) * 8 + k0;
#pragma unroll
    for (int mt = 0; mt < 4; mt++)
        ldsm_x4(a[mt][0], a[mt][1], a[mt][2], a[mt][3],
                smA + (wm + mt * 16 + lrow) * PITCHB + lcol * 2);
}
__device__ __forceinline__ void ldB(uint32_t smB, int wn, int lane, int k0, uint32_t b[4][2]) {
    int brow = ((lane >> 4) & 1) * 8 + (lane & 7);
    int bcol = ((lane >> 3) & 1) * 8 + k0;
#pragma unroll
    for (int j2 = 0; j2 < 2; j2++) {
        uint32_t r0, r1, r2, r3;
        ldsm_x4(r0, r1, r2, r3, smB + (wn + j2 * 16 + brow) * PITCHB + bcol * 2);
        b[j2 * 2][0] = r0; b[j2 * 2][1] = r1;
        b[j2 * 2 + 1][0] = r2; b[j2 * 2 + 1][1] = r3;
    }
}

__device__ __forceinline__ void gemm_mainloop(const __half* A, const __half* B,
                                              uint32_t smb, int tid, float acc[4][4][4])
{
    const int wid = tid >> 5, lane = tid & 31;
    const int wm = (wid >> 2) * 64, wn = (wid & 3) * 32;
    const int NCH = Kdim / KCc;  // 32

    load_chunk(A, B, smb,             0, tid); cp_commit();
    load_chunk(A, B, smb + BUF_BYTES, 1, tid); cp_commit();

    int stage = 0, wstage = 2;
    for (int c = 0; c < NCH; ++c) {
        uint32_t buf = smb + stage * BUF_BYTES;
        cp_wait1();
        __syncthreads();

        uint32_t smA = buf, smB = buf + TILE_BYTES;
#pragma unroll
        for (int ks = 0; ks < 2; ks++) {
            int k0 = ks * 16;
            uint32_t aa[4][4], bb[4][2];
            ldA(smA, wm, lane, k0, aa);
            ldB(smB, wn, lane, k0, bb);
#pragma unroll
            for (int mt = 0; mt < 4; mt++)
#pragma unroll
                for (int nt = 0; nt < 4; nt++) mma_f16(acc[mt][nt], aa[mt], bb[nt]);
        }
        if (c + 2 < NCH)
            load_chunk(A, B, smb + wstage * BUF_BYTES, c + 2, tid);
        cp_commit();
        stage = (stage + 1) % 3; wstage = (wstage + 1) % 3;
    }
}

// ---------------------------------------------------------------------------
// QKV GEMM (fp16 1-pass): epilogue writes single fp16 head-major [b,h,n,d]
// ---------------------------------------------------------------------------
__global__ __launch_bounds__(256) void qkv_mma_kernel()
{
    extern __shared__ char sm[];
    uint32_t smb = smem_u32(sm);
    int tid = threadIdx.x;
    int z = blockIdx.z;
    int n0 = blockIdx.x * BNt;
    int m0 = blockIdx.y * BMt;

    const __half* A = (z == 0 ? g_X : g_X2) + (size_t)m0 * Kdim;
    const __half* B = g_Wq + (size_t)(z * Hh + n0) * Kdim;

    float acc[4][4][4];
#pragma unroll
    for (int i = 0; i < 4; i++)
#pragma unroll
        for (int j = 0; j < 4; j++)
#pragma unroll
            for (int k = 0; k < 4; k++) acc[i][j][k] = 0.f;

    gemm_mainloop(A, B, smb, tid, acc);

    __half* dst = (z == 0) ? g_Qh : (z == 1) ? g_Kh : g_Vh;
    const int wid = tid >> 5, lane = tid & 31;
    const int wm = (wid >> 2) * 64, wn = (wid & 3) * 32;
#pragma unroll
    for (int mt = 0; mt < 4; mt++) {
#pragma unroll
        for (int nt = 0; nt < 4; nt++) {
            int col = n0 + wn + nt * 8 + (lane & 3) * 2;
            int h = col >> 6, d = col & 63;
#pragma unroll
            for (int half = 0; half < 2; half++) {
                int gm = m0 + wm + mt * 16 + (lane >> 2) + half * 8;
                int b = gm / Nn, n = gm % Nn;
                size_t idx = ((((size_t)b * NH + h) * Nn) + n) * HD + d;
                *(uint32_t*)(dst + idx) = packh(acc[mt][nt][half * 2],
                                                acc[mt][nt][half * 2 + 1]);
            }
        }
    }
}

// ---------------------------------------------------------------------------
// Output projection GEMM (fp16 1-pass): out = attn @ Wout + bout (fp32 out)
// ---------------------------------------------------------------------------
__global__ __launch_bounds__(256) void proj_mma_kernel(const float* __restrict__ bout,
                                                       float* __restrict__ out)
{
    extern __shared__ char sm[];
    uint32_t smb = smem_u32(sm);
    int tid = threadIdx.x;
    int n0 = blockIdx.x * BNt;
    int m0 = blockIdx.y * BMt;

    const __half* A = g_Ah + (size_t)m0 * Kdim;
    const __half* B = g_Wo + (size_t)n0 * Kdim;

    float acc[4][4][4];
#pragma unroll
    for (int i = 0; i < 4; i++)
#pragma unroll
        for (int j = 0; j < 4; j++)
#pragma unroll
            for (int k = 0; k < 4; k++) acc[i][j][k] = 0.f;

    gemm_mainloop(A, B, smb, tid, acc);

    const int wid = tid >> 5, lane = tid & 31;
    const int wm = (wid >> 2) * 64, wn = (wid & 3) * 32;
#pragma unroll
    for (int mt = 0; mt < 4; mt++) {
#pragma unroll
        for (int nt = 0; nt < 4; nt++) {
            int col = n0 + wn + nt * 8 + (lane & 3) * 2;
            float2 bb = *(const float2*)(bout + col);
#pragma unroll
            for (int half = 0; half < 2; half++) {
                int gm = m0 + wm + mt * 16 + (lane >> 2) + half * 8;
                float2 o = make_float2(acc[mt][nt][half * 2] + bb.x,
                                       acc[mt][nt][half * 2 + 1] + bb.y);
                *(float2*)(out + (size_t)gm * 1024 + col) = o;
            }
        }
    }
}

// ---------------------------------------------------------------------------
// Tensor-core flash attention — single-pass fp16 (unchanged from round 8,
// epilogue now emits single fp16 A)
// ---------------------------------------------------------------------------
#define APITCHB 144
#define QT 128
#define KVT 64
#define MATB (64*APITCHB)              // 9216 per kv matrix
#define KVBUF (2*MATB)                 // K|V = 18432
#define QBYTES (128*APITCHB)           // 18432
#define ATTN_SMEM (QBYTES + 3*KVBUF)   // 73728

__device__ __forceinline__ void load_kv_tile(const __half* K, const __half* V,
                                             uint32_t bufb, int t, int tid)
{
#pragma unroll
    for (int i = 0; i < 4; i++) {
        int e = tid + i * 256;
        int mat = e >> 9;            // 0 = K, 1 = V
        int row = (e >> 3) & 63;
        int c   = e & 7;
        const __half* src = (mat == 0 ? K : V) + ((size_t)(t * KVT + row)) * HD + c * 8;
        cp_async16(bufb + mat * MATB + row * APITCHB + c * 16, src);
    }
}

__global__ __launch_bounds__(256) void attn_mma_kernel()
{
    extern __shared__ char sm[];
    uint32_t smb = smem_u32(sm);
    const uint32_t QS  = smb;
    const uint32_t KV0 = smb + QBYTES;

    const int tid = threadIdx.x, lane = tid & 31, wid = tid >> 5;
    const int bh = blockIdx.y, q0 = blockIdx.x * QT;

    const size_t base = (size_t)bh * Nn * HD;
    const __half* Qp = g_Qh + base + (size_t)q0 * HD;
    const __half* Kp = g_Kh + base;
    const __half* Vp = g_Vh + base;

#pragma unroll
    for (int i = 0; i < 4; i++) {
        int e = tid + i * 256;
        int row = e >> 3;
        int c   = e & 7;
        cp_async16(QS + row * APITCHB + c * 16, Qp + (size_t)row * HD + c * 8);
    }
    cp_commit();
    load_kv_tile(Kp, Vp, KV0, 0, tid);          cp_commit();
    load_kv_tile(Kp, Vp, KV0 + KVBUF, 1, tid);  cp_commit();

    cp_wait2();
    __syncthreads();

    uint32_t aq[4][4];
    {
        int lrow = lane & 15;
        int lcolB = (lane >> 4) * 16;
        uint32_t qrow = (wid * 16 + lrow) * APITCHB + lcolB;
#pragma unroll
        for (int kt = 0; kt < 4; kt++)
            ldsm_x4(aq[kt][0], aq[kt][1], aq[kt][2], aq[kt][3], QS + qrow + kt * 32);
    }

    float O[8][4];
#pragma unroll
    for (int i = 0; i < 8; i++)
#pragma unroll
        for (int j = 0; j < 4; j++) O[i][j] = 0.f;
    float m0 = -INFINITY, m1 = -INFINITY, l0 = 0.f, l1 = 0.f;
    const float cc = SCALE * 1.4426950408889634f;

    const int brow = ((lane >> 4) & 1) * 8 + (lane & 7);
    const int bcolB = ((lane >> 3) & 1) * 16;
    const int vrow = lane & 15;
    const int vcolB = ((lane >> 4) & 1) * 16;

    int stage = 0, wstage = 2;
    for (int t = 0; t < Nn / KVT; ++t) {
        uint32_t buf = KV0 + stage * KVBUF;
        cp_wait1();
        __syncthreads();

        uint32_t Kb = buf, Vb = buf + MATB;

        float S[8][4];
#pragma unroll
        for (int i = 0; i < 8; i++)
#pragma unroll
            for (int j = 0; j < 4; j++) S[i][j] = 0.f;

        uint32_t bk[8][2];
#pragma unroll
        for (int kt = 0; kt < 4; kt++) {
            uint32_t colB = kt * 32 + bcolB;
#pragma unroll
            for (int g = 0; g < 4; g++)
                ldsm_x4(bk[2 * g][0], bk[2 * g][1], bk[2 * g + 1][0], bk[2 * g + 1][1],
                        Kb + (g * 16 + brow) * APITCHB + colB);
#pragma unroll
            for (int nt = 0; nt < 8; nt++) mma_f16(S[nt], aq[kt], bk[nt]);
        }

        float rm0 = -INFINITY, rm1 = -INFINITY;
#pragma unroll
        for (int j = 0; j < 8; j++) {
            rm0 = fmaxf(rm0, fmaxf(S[j][0], S[j][1]));
            rm1 = fmaxf(rm1, fmaxf(S[j][2], S[j][3]));
        }
        rm0 = fmaxf(rm0, __shfl_xor_sync(0xffffffffu, rm0, 1));
        rm0 = fmaxf(rm0, __shfl_xor_sync(0xffffffffu, rm0, 2));
        rm1 = fmaxf(rm1, __shfl_xor_sync(0xffffffffu, rm1, 1));
        rm1 = fmaxf(rm1, __shfl_xor_sync(0xffffffffu, rm1, 2));
        float mn0 = fmaxf(m0, rm0), mn1 = fmaxf(m1, rm1);
        float a0 = ex2f((m0 - mn0) * cc), a1 = ex2f((m1 - mn1) * cc);
        m0 = mn0; m1 = mn1;
        float mc0 = mn0 * cc, mc1 = mn1 * cc;

        uint32_t ph[4][4];
        float rs0 = 0.f, rs1 = 0.f;
#pragma unroll
        for (int j = 0; j < 8; j++) {
            float p0 = ex2f(fmaf(S[j][0], cc, -mc0));
            float p1 = ex2f(fmaf(S[j][1], cc, -mc0));
            float p2 = ex2f(fmaf(S[j][2], cc, -mc1));
            float p3 = ex2f(fmaf(S[j][3], cc, -mc1));
            rs0 += p0 + p1; rs1 += p2 + p3;
            int kt = j >> 1, hf = (j & 1) * 2;
            ph[kt][hf]     = packh(p0, p1);
            ph[kt][hf + 1] = packh(p2, p3);
        }
        rs0 += __shfl_xor_sync(0xffffffffu, rs0, 1);
        rs0 += __shfl_xor_sync(0xffffffffu, rs0, 2);
        rs1 += __shfl_xor_sync(0xffffffffu, rs1, 1);
        rs1 += __shfl_xor_sync(0xffffffffu, rs1, 2);
        l0 = l0 * a0 + rs0;
        l1 = l1 * a1 + rs1;
#pragma unroll
        for (int dt = 0; dt < 8; dt++) {
            O[dt][0] *= a0; O[dt][1] *= a0; O[dt][2] *= a1; O[dt][3] *= a1;
        }

        uint32_t bv[8][2];
#pragma unroll
        for (int kt = 0; kt < 4; kt++) {
            uint32_t rowB = (kt * 16 + vrow) * APITCHB + vcolB;
#pragma unroll
            for (int g2 = 0; g2 < 4; g2++)
                ldsm_x4_t(bv[2 * g2][0], bv[2 * g2][1], bv[2 * g2 + 1][0], bv[2 * g2 + 1][1],
                          Vb + rowB + g2 * 32);
#pragma unroll
            for (int dt = 0; dt < 8; dt++) mma_f16(O[dt], ph[kt], bv[dt]);
        }

        if (t + 2 < Nn / KVT)
            load_kv_tile(Kp, Vp, KV0 + wstage * KVBUF, t + 2, tid);
        cp_commit();
        stage = (stage + 1) % 3; wstage = (wstage + 1) % 3;
    }

    // epilogue: normalize, write single fp16 to g_Ah [b*n][h*64+d]
    const int b = bh >> 4, h = bh & 15;
    float il0 = 1.f / l0, il1 = 1.f / l1;
    size_t row0 = (size_t)b * Nn + q0 + wid * 16 + (lane >> 2);
    size_t row1 = row0 + 8;
#pragma unroll
    for (int dt = 0; dt < 8; dt++) {
        int col = h * 64 + dt * 8 + (lane & 3) * 2;
        *(uint32_t*)(g_Ah + row0 * Hh + col) = packh(O[dt][0] * il0, O[dt][1] * il0);
        *(uint32_t*)(g_Ah + row1 * Hh + col) = packh(O[dt][2] * il1, O[dt][3] * il1);
    }
}

// ---------------------------------------------------------------------------
extern "C" void kernel_launch(void* const* d_in, const int* in_sizes, int n_in,
                              void* d_out, int out_size)
{
    const float* x    = (const float*)d_in[0];
    const float* x2   = (const float*)d_in[1];
    const float* Wqkv = (const float*)d_in[2];
    const float* Wout = (const float*)d_in[3];
    const float* bout = (const float*)d_in[4];
    float* out = (float*)d_out;

    // 0) fp32 -> fp16 converts (+ weight transposes)
    {
        __half *xp, *x2p, *wq, *wo;
        cudaGetSymbolAddress((void**)&xp,  g_X);
        cudaGetSymbolAddress((void**)&x2p, g_X2);
        cudaGetSymbolAddress((void**)&wq,  g_Wq);
        cudaGetSymbolAddress((void**)&wo,  g_Wo);

        int n4 = M_TOT * Kdim / 4;
        conv_kernel<<<(n4 + 255) / 256, 256>>>(x,  xp,  n4);
        conv_kernel<<<(n4 + 255) / 256, 256>>>(x2, x2p, n4);
        tconv_kernel<<<dim3(3 * Hh / 32, Kdim / 32), dim3(32, 8)>>>(Wqkv, wq, 3 * Hh);
        tconv_kernel<<<dim3(Hh / 32,     Kdim / 32), dim3(32, 8)>>>(Wout, wo, Hh);
    }

    // 1) QKV projections (fp16 1-pass HMMA)
    cudaFuncSetAttribute(qkv_mma_kernel, cudaFuncAttributeMaxDynamicSharedMemorySize, GEMM_SMEM);
    qkv_mma_kernel<<<dim3(Hh / BNt, M_TOT / BMt, 3), 256, GEMM_SMEM>>>();

    // 2) Tensor-core flash attention (single-pass fp16)
    cudaFuncSetAttribute(attn_mma_kernel, cudaFuncAttributeMaxDynamicSharedMemorySize, ATTN_SMEM);
    attn_mma_kernel<<<dim3(Nn / QT, Bb * NH), 256, ATTN_SMEM>>>();

    // 3) Output projection (fp16 1-pass HMMA)
    cudaFuncSetAttribute(proj_mma_kernel, cudaFuncAttributeMaxDynamicSharedMemorySize, GEMM_SMEM);
    proj_mma_kernel<<<dim3(Hh / BNt, M_TOT / BMt), 256, GEMM_SMEM>>>(bout, out);
}

// round 10
// speedup vs baseline: 4.2308x; 1.0095x over previous
#include <cuda_runtime.h>
#include <cuda_fp16.h>
#include <math.h>
#include <stdint.h>

// Problem constants
#define Bb 2
#define Nn 2048
#define Hh 1024
#define NH 16
#define HD 64
#define SCALE 0.125f
#define Kdim 1024
#define M_TOT (Bb*Nn)   // 4096

// ---------------------------------------------------------------------------
// Scratch (device globals; no allocations allowed)
// ---------------------------------------------------------------------------
__device__ __align__(128) __half g_X  [M_TOT*Kdim];     // x fp16
__device__ __align__(128) __half g_X2 [M_TOT*Kdim];     // x2 fp16
__device__ __align__(128) __half g_Wq [3*Hh*Kdim];      // Wqkv^T [3072][1024] fp16
__device__ __align__(128) __half g_Wo [Hh*Kdim];        // Wout^T fp16
// Q/K/V single fp16, head-major [b,h,n,d]
__device__ __align__(128) __half g_Qh[Bb*NH*Nn*HD];
__device__ __align__(128) __half g_Kh[Bb*NH*Nn*HD];
__device__ __align__(128) __half g_Vh[Bb*NH*Nn*HD];
// attention out single fp16 [b*n][h*d]
__device__ __align__(128) __half g_Ah[M_TOT*Hh];

// ---------------------------------------------------------------------------
// PTX helpers
// ---------------------------------------------------------------------------
__device__ __forceinline__ uint32_t smem_u32(const void* p) {
    return (uint32_t)__cvta_generic_to_shared(p);
}
__device__ __forceinline__ void cp_async16(uint32_t d, const void* s) {
    asm volatile("cp.async.cg.shared.global [%0], [%1], 16;\n" :: "r"(d), "l"(s) : "memory");
}
__device__ __forceinline__ void cp_commit() { asm volatile("cp.async.commit_group;\n" ::: "memory"); }
__device__ __forceinline__ void cp_wait1()  { asm volatile("cp.async.wait_group 1;\n" ::: "memory"); }
__device__ __forceinline__ void cp_wait2()  { asm volatile("cp.async.wait_group 2;\n" ::: "memory"); }
__device__ __forceinline__ void ldsm_x4(uint32_t& r0, uint32_t& r1, uint32_t& r2, uint32_t& r3, uint32_t a) {
    asm volatile("ldmatrix.sync.aligned.m8n8.x4.shared.b16 {%0,%1,%2,%3}, [%4];"
                 : "=r"(r0), "=r"(r1), "=r"(r2), "=r"(r3) : "r"(a));
}
__device__ __forceinline__ void ldsm_x4_t(uint32_t& r0, uint32_t& r1, uint32_t& r2, uint32_t& r3, uint32_t a) {
    asm volatile("ldmatrix.sync.aligned.m8n8.x4.trans.shared.b16 {%0,%1,%2,%3}, [%4];"
                 : "=r"(r0), "=r"(r1), "=r"(r2), "=r"(r3) : "r"(a));
}
__device__ __forceinline__ void mma_f16(float c[4], const uint32_t a[4], const uint32_t b[2]) {
    asm volatile("mma.sync.aligned.m16n8k16.row.col.f32.f16.f16.f32 "
                 "{%0,%1,%2,%3}, {%4,%5,%6,%7}, {%8,%9}, {%0,%1,%2,%3};"
                 : "+f"(c[0]), "+f"(c[1]), "+f"(c[2]), "+f"(c[3])
                 : "r"(a[0]), "r"(a[1]), "r"(a[2]), "r"(a[3]), "r"(b[0]), "r"(b[1]));
}
__device__ __forceinline__ float ex2f(float x) {
    float y; asm("ex2.approx.f32 %0, %1;" : "=f"(y) : "f"(x)); return y;
}
__device__ __forceinline__ uint32_t packh(float a, float b) {
    __half2 v = __halves2half2(__float2half_rn(a), __float2half_rn(b));
    return *(uint32_t*)&v;
}

// ---------------------------------------------------------------------------
// GEMM tiling: single fp16 A and B -> 2 tiles per chunk
// ---------------------------------------------------------------------------
#define BMt 128
#define BNt 128
#define KCc 32
#define PITCHB 80
#define TILE_BYTES (128*PITCHB)     // 10240
#define BUF_BYTES (2*TILE_BYTES)    // A|B = 20480
#define GEMM_SMEM (3*BUF_BYTES)     // 61440

// ---------------------------------------------------------------------------
// fp32 -> fp16 convert (element-wise, both streams in one launch)
// ---------------------------------------------------------------------------
__global__ __launch_bounds__(256) void conv2_kernel(const float* __restrict__ s0,
                                                    const float* __restrict__ s1,
                                                    __half* __restrict__ d0,
                                                    __half* __restrict__ d1, int n4)
{
    int i = blockIdx.x * blockDim.x + threadIdx.x;
    if (i >= n4) return;
    const float* src = blockIdx.y ? s1 : s0;
    __half* dst = blockIdx.y ? d1 : d0;
    float4 v = ((const float4*)src)[i];
    __half2* D = (__half2*)(dst + (size_t)i * 4);
    D[0] = __halves2half2(__float2half_rn(v.x), __float2half_rn(v.y));
    D[1] = __halves2half2(__float2half_rn(v.z), __float2half_rn(v.w));
}

// Transpose + convert: src [1024][C] fp32 -> dst [C][1024] fp16
__global__ __launch_bounds__(256) void tconv_kernel(const float* __restrict__ src,
                                                    __half* __restrict__ dst, int C)
{
    __shared__ float tile[32][33];
    int c0 = blockIdx.x * 32, k0 = blockIdx.y * 32;
    int tx = threadIdx.x, ty = threadIdx.y;  // 32x8
#pragma unroll
    for (int i = 0; i < 32; i += 8)
        tile[ty + i][tx] = src[(size_t)(k0 + ty + i) * C + c0 + tx];
    __syncthreads();
#pragma unroll
    for (int i = 0; i < 32; i += 8)
        dst[(size_t)(c0 + ty + i) * 1024 + k0 + tx] = __float2half_rn(tile[tx][ty + i]);
}

// ---------------------------------------------------------------------------
// fp16 single-pass HMMA GEMM mainloop: C[128,128] = A @ B^T, K=1024
// ---------------------------------------------------------------------------
__device__ __forceinline__ void load_chunk(const __half* A, const __half* B,
                                           uint32_t smbuf, int c, int tid)
{
    int row  = tid >> 1;
    int half = (tid & 1) * 2;
    size_t g = (size_t)row * Kdim + (size_t)c * KCc + half * 8;
    uint32_t s = smbuf + row * PITCHB + half * 16;
    cp_async16(s,                   A + g);
    cp_async16(s + 16,              A + g + 8);
    cp_async16(s + TILE_BYTES,      B + g);
    cp_async16(s + TILE_BYTES + 16, B + g + 8);
}

__device__ __forceinline__ void ldA(uint32_t smA, int wm, int lane, int k0, uint32_t a[4][4]) {
    int lrow = lane & 15;
    int lcol = (lane >> 4) * 8 + k0;
#pragma unroll
    for (int mt = 0; mt < 4; mt++)
        ldsm_x4(a[mt][0], a[mt][1], a[mt][2], a[mt][3],
                smA + (wm + mt * 16 + lrow) * PITCHB + lcol * 2);
}
__device__ __forceinline__ void ldB(uint32_t smB, int wn, int lane, int k0, uint32_t b[4][2]) {
    int brow = ((lane >> 4) & 1) * 8 + (lane & 7);
    int bcol = ((lane >> 3) & 1) * 8 + k0;
#pragma unroll
    for (int j2 = 0; j2 < 2; j2++) {
        uint32_t r0, r1, r2, r3;
        ldsm_x4(r0, r1, r2, r3, smB + (wn + j2 * 16 + brow) * PITCHB + bcol * 2);
        b[j2 * 2][0] = r0; b[j2 * 2][1] = r1;
        b[j2 * 2 + 1][0] = r2; b[j2 * 2 + 1][1] = r3;
    }
}

__device__ __forceinline__ void gemm_mainloop(const __half* A, const __half* B,
                                              uint32_t smb, int tid, float acc[4][4][4])
{
    const int wid = tid >> 5, lane = tid & 31;
    const int wm = (wid >> 2) * 64, wn = (wid & 3) * 32;
    const int NCH = Kdim / KCc;  // 32

    load_chunk(A, B, smb,             0, tid); cp_commit();
    load_chunk(A, B, smb + BUF_BYTES, 1, tid); cp_commit();

    int stage = 0, wstage = 2;
    for (int c = 0; c < NCH; ++c) {
        uint32_t buf = smb + stage * BUF_BYTES;
        cp_wait1();
        __syncthreads();

        uint32_t smA = buf, smB = buf + TILE_BYTES;
#pragma unroll
        for (int ks = 0; ks < 2; ks++) {
            int k0 = ks * 16;
            uint32_t aa[4][4], bb[4][2];
            ldA(smA, wm, lane, k0, aa);
            ldB(smB, wn, lane, k0, bb);
#pragma unroll
            for (int mt = 0; mt < 4; mt++)
#pragma unroll
                for (int nt = 0; nt < 4; nt++) mma_f16(acc[mt][nt], aa[mt], bb[nt]);
        }
        if (c + 2 < NCH)
            load_chunk(A, B, smb + wstage * BUF_BYTES, c + 2, tid);
        cp_commit();
        stage = (stage + 1) % 3; wstage = (wstage + 1) % 3;
    }
}

// ---------------------------------------------------------------------------
// QKV GEMM (fp16 1-pass): epilogue writes single fp16 head-major [b,h,n,d]
// ---------------------------------------------------------------------------
__global__ __launch_bounds__(256, 2) void qkv_mma_kernel()
{
    extern __shared__ char sm[];
    uint32_t smb = smem_u32(sm);
    int tid = threadIdx.x;
    int z = blockIdx.z;
    int n0 = blockIdx.x * BNt;
    int m0 = blockIdx.y * BMt;

    const __half* A = (z == 0 ? g_X : g_X2) + (size_t)m0 * Kdim;
    const __half* B = g_Wq + (size_t)(z * Hh + n0) * Kdim;

    float acc[4][4][4];
#pragma unroll
    for (int i = 0; i < 4; i++)
#pragma unroll
        for (int j = 0; j < 4; j++)
#pragma unroll
            for (int k = 0; k < 4; k++) acc[i][j][k] = 0.f;

    gemm_mainloop(A, B, smb, tid, acc);

    __half* dst = (z == 0) ? g_Qh : (z == 1) ? g_Kh : g_Vh;
    const int wid = tid >> 5, lane = tid & 31;
    const int wm = (wid >> 2) * 64, wn = (wid & 3) * 32;
#pragma unroll
    for (int mt = 0; mt < 4; mt++) {
#pragma unroll
        for (int nt = 0; nt < 4; nt++) {
            int col = n0 + wn + nt * 8 + (lane & 3) * 2;
            int h = col >> 6, d = col & 63;
#pragma unroll
            for (int half = 0; half < 2; half++) {
                int gm = m0 + wm + mt * 16 + (lane >> 2) + half * 8;
                int b = gm / Nn, n = gm % Nn;
                size_t idx = ((((size_t)b * NH + h) * Nn) + n) * HD + d;
                *(uint32_t*)(dst + idx) = packh(acc[mt][nt][half * 2],
                                                acc[mt][nt][half * 2 + 1]);
            }
        }
    }
}

// ---------------------------------------------------------------------------
// Output projection GEMM (fp16 1-pass): out = attn @ Wout + bout (fp32 out)
// ---------------------------------------------------------------------------
__global__ __launch_bounds__(256, 2) void proj_mma_kernel(const float* __restrict__ bout,
                                                          float* __restrict__ out)
{
    extern __shared__ char sm[];
    uint32_t smb = smem_u32(sm);
    int tid = threadIdx.x;
    int n0 = blockIdx.x * BNt;
    int m0 = blockIdx.y * BMt;

    const __half* A = g_Ah + (size_t)m0 * Kdim;
    const __half* B = g_Wo + (size_t)n0 * Kdim;

    float acc[4][4][4];
#pragma unroll
    for (int i = 0; i < 4; i++)
#pragma unroll
        for (int j = 0; j < 4; j++)
#pragma unroll
            for (int k = 0; k < 4; k++) acc[i][j][k] = 0.f;

    gemm_mainloop(A, B, smb, tid, acc);

    const int wid = tid >> 5, lane = tid & 31;
    const int wm = (wid >> 2) * 64, wn = (wid & 3) * 32;
#pragma unroll
    for (int mt = 0; mt < 4; mt++) {
#pragma unroll
        for (int nt = 0; nt < 4; nt++) {
            int col = n0 + wn + nt * 8 + (lane & 3) * 2;
            float2 bb = *(const float2*)(bout + col);
#pragma unroll
            for (int half = 0; half < 2; half++) {
                int gm = m0 + wm + mt * 16 + (lane >> 2) + half * 8;
                float2 o = make_float2(acc[mt][nt][half * 2] + bb.x,
                                       acc[mt][nt][half * 2 + 1] + bb.y);
                *(float2*)(out + (size_t)gm * 1024 + col) = o;
            }
        }
    }
}

// ---------------------------------------------------------------------------
// Tensor-core flash attention — single-pass fp16, KV tile = 128
// ---------------------------------------------------------------------------
#define APITCHB 144
#define QT 128
#define KVT 128
#define MATB (128*APITCHB)             // 18432 per kv matrix
#define KVBUF (2*MATB)                 // K|V = 36864
#define QBYTES (128*APITCHB)           // 18432
#define ATTN_SMEM (QBYTES + 3*KVBUF)   // 129024

__device__ __forceinline__ void load_kv_tile(const __half* K, const __half* V,
                                             uint32_t bufb, int t, int tid)
{
#pragma unroll
    for (int i = 0; i < 8; i++) {
        int e = tid + i * 256;
        int mat = e >> 10;           // 0 = K, 1 = V
        int row = (e >> 3) & 127;
        int c   = e & 7;
        const __half* src = (mat == 0 ? K : V) + ((size_t)(t * KVT + row)) * HD + c * 8;
        cp_async16(bufb + mat * MATB + row * APITCHB + c * 16, src);
    }
}

__global__ __launch_bounds__(256, 1) void attn_mma_kernel()
{
    extern __shared__ char sm[];
    uint32_t smb = smem_u32(sm);
    const uint32_t QS  = smb;
    const uint32_t KV0 = smb + QBYTES;

    const int tid = threadIdx.x, lane = tid & 31, wid = tid >> 5;
    const int bh = blockIdx.y, q0 = blockIdx.x * QT;

    const size_t base = (size_t)bh * Nn * HD;
    const __half* Qp = g_Qh + base + (size_t)q0 * HD;
    const __half* Kp = g_Kh + base;
    const __half* Vp = g_Vh + base;

#pragma unroll
    for (int i = 0; i < 4; i++) {
        int e = tid + i * 256;
        int row = e >> 3;
        int c   = e & 7;
        cp_async16(QS + row * APITCHB + c * 16, Qp + (size_t)row * HD + c * 8);
    }
    cp_commit();
    load_kv_tile(Kp, Vp, KV0, 0, tid);          cp_commit();
    load_kv_tile(Kp, Vp, KV0 + KVBUF, 1, tid);  cp_commit();

    cp_wait2();
    __syncthreads();

    uint32_t aq[4][4];
    {
        int lrow = lane & 15;
        int lcolB = (lane >> 4) * 16;
        uint32_t qrow = (wid * 16 + lrow) * APITCHB + lcolB;
#pragma unroll
        for (int kt = 0; kt < 4; kt++)
            ldsm_x4(aq[kt][0], aq[kt][1], aq[kt][2], aq[kt][3], QS + qrow + kt * 32);
    }

    float O[8][4];
#pragma unroll
    for (int i = 0; i < 8; i++)
#pragma unroll
        for (int j = 0; j < 4; j++) O[i][j] = 0.f;
    float m0 = -INFINITY, m1 = -INFINITY, l0 = 0.f, l1 = 0.f;
    const float cc = SCALE * 1.4426950408889634f;

    const int brow = ((lane >> 4) & 1) * 8 + (lane & 7);
    const int bcolB = ((lane >> 3) & 1) * 16;
    const int vrow = lane & 15;
    const int vcolB = ((lane >> 4) & 1) * 16;

    int stage = 0, wstage = 2;
    for (int t = 0; t < Nn / KVT; ++t) {
        uint32_t buf = KV0 + stage * KVBUF;
        cp_wait1();
        __syncthreads();

        uint32_t Kb = buf, Vb = buf + MATB;

        // ---- S = Q K^T over 128 KV columns (two 64-col halves) ----
        float S[16][4];
#pragma unroll
        for (int i = 0; i < 16; i++)
#pragma unroll
            for (int j = 0; j < 4; j++) S[i][j] = 0.f;

#pragma unroll
        for (int hh = 0; hh < 2; hh++) {
            uint32_t Kbh = Kb + (hh * 64) * APITCHB;
            uint32_t bk[8][2];
#pragma unroll
            for (int kt = 0; kt < 4; kt++) {
                uint32_t colB = kt * 32 + bcolB;
#pragma unroll
                for (int g = 0; g < 4; g++)
                    ldsm_x4(bk[2 * g][0], bk[2 * g][1], bk[2 * g + 1][0], bk[2 * g + 1][1],
                            Kbh + (g * 16 + brow) * APITCHB + colB);
#pragma unroll
                for (int nt = 0; nt < 8; nt++) mma_f16(S[hh * 8 + nt], aq[kt], bk[nt]);
            }
        }

        // ---- online softmax over 128 columns ----
        float rm0 = -INFINITY, rm1 = -INFINITY;
#pragma unroll
        for (int j = 0; j < 16; j++) {
            rm0 = fmaxf(rm0, fmaxf(S[j][0], S[j][1]));
            rm1 = fmaxf(rm1, fmaxf(S[j][2], S[j][3]));
        }
        rm0 = fmaxf(rm0, __shfl_xor_sync(0xffffffffu, rm0, 1));
        rm0 = fmaxf(rm0, __shfl_xor_sync(0xffffffffu, rm0, 2));
        rm1 = fmaxf(rm1, __shfl_xor_sync(0xffffffffu, rm1, 1));
        rm1 = fmaxf(rm1, __shfl_xor_sync(0xffffffffu, rm1, 2));
        float mn0 = fmaxf(m0, rm0), mn1 = fmaxf(m1, rm1);
        float a0 = ex2f((m0 - mn0) * cc), a1 = ex2f((m1 - mn1) * cc);
        m0 = mn0; m1 = mn1;
        float mc0 = mn0 * cc, mc1 = mn1 * cc;

        uint32_t ph[8][4];
        float rs0 = 0.f, rs1 = 0.f;
#pragma unroll
        for (int j = 0; j < 16; j++) {
            float p0 = ex2f(fmaf(S[j][0], cc, -mc0));
            float p1 = ex2f(fmaf(S[j][1], cc, -mc0));
            float p2 = ex2f(fmaf(S[j][2], cc, -mc1));
            float p3 = ex2f(fmaf(S[j][3], cc, -mc1));
            rs0 += p0 + p1; rs1 += p2 + p3;
            int kt = j >> 1, hf = (j & 1) * 2;
            ph[kt][hf]     = packh(p0, p1);
            ph[kt][hf + 1] = packh(p2, p3);
        }
        rs0 += __shfl_xor_sync(0xffffffffu, rs0, 1);
        rs0 += __shfl_xor_sync(0xffffffffu, rs0, 2);
        rs1 += __shfl_xor_sync(0xffffffffu, rs1, 1);
        rs1 += __shfl_xor_sync(0xffffffffu, rs1, 2);
        l0 = l0 * a0 + rs0;
        l1 = l1 * a1 + rs1;
#pragma unroll
        for (int dt = 0; dt < 8; dt++) {
            O[dt][0] *= a0; O[dt][1] *= a0; O[dt][2] *= a1; O[dt][3] *= a1;
        }

        // ---- O += P V over 128 KV rows ----
#pragma unroll
        for (int kt = 0; kt < 8; kt++) {
            uint32_t bv[8][2];
            uint32_t rowB = (kt * 16 + vrow) * APITCHB + vcolB;
#pragma unroll
            for (int g2 = 0; g2 < 4; g2++)
                ldsm_x4_t(bv[2 * g2][0], bv[2 * g2][1], bv[2 * g2 + 1][0], bv[2 * g2 + 1][1],
                          Vb + rowB + g2 * 32);
#pragma unroll
            for (int dt = 0; dt < 8; dt++) mma_f16(O[dt], ph[kt], bv[dt]);
        }

        if (t + 2 < Nn / KVT)
            load_kv_tile(Kp, Vp, KV0 + wstage * KVBUF, t + 2, tid);
        cp_commit();
        stage = (stage + 1) % 3; wstage = (wstage + 1) % 3;
    }

    // epilogue: normalize, write single fp16 to g_Ah [b*n][h*64+d]
    const int b = bh >> 4, h = bh & 15;
    float il0 = 1.f / l0, il1 = 1.f / l1;
    size_t row0 = (size_t)b * Nn + q0 + wid * 16 + (lane >> 2);
    size_t row1 = row0 + 8;
#pragma unroll
    for (int dt = 0; dt < 8; dt++) {
        int col = h * 64 + dt * 8 + (lane & 3) * 2;
        *(uint32_t*)(g_Ah + row0 * Hh + col) = packh(O[dt][0] * il0, O[dt][1] * il0);
        *(uint32_t*)(g_Ah + row1 * Hh + col) = packh(O[dt][2] * il1, O[dt][3] * il1);
    }
}

// ---------------------------------------------------------------------------
extern "C" void kernel_launch(void* const* d_in, const int* in_sizes, int n_in,
                              void* d_out, int out_size)
{
    const float* x    = (const float*)d_in[0];
    const float* x2   = (const float*)d_in[1];
    const float* Wqkv = (const float*)d_in[2];
    const float* Wout = (const float*)d_in[3];
    const float* bout = (const float*)d_in[4];
    float* out = (float*)d_out;

    // 0) fp32 -> fp16 converts (+ weight transposes)
    {
        __half *xp, *x2p, *wq, *wo;
        cudaGetSymbolAddress((void**)&xp,  g_X);
        cudaGetSymbolAddress((void**)&x2p, g_X2);
        cudaGetSymbolAddress((void**)&wq,  g_Wq);
        cudaGetSymbolAddress((void**)&wo,  g_Wo);

        int n4 = M_TOT * Kdim / 4;
        conv2_kernel<<<dim3((n4 + 255) / 256, 2), 256>>>(x, x2, xp, x2p, n4);
        tconv_kernel<<<dim3(3 * Hh / 32, Kdim / 32), dim3(32, 8)>>>(Wqkv, wq, 3 * Hh);
        tconv_kernel<<<dim3(Hh / 32,     Kdim / 32), dim3(32, 8)>>>(Wout, wo, Hh);
    }

    // 1) QKV projections (fp16 1-pass HMMA)
    cudaFuncSetAttribute(qkv_mma_kernel, cudaFuncAttributeMaxDynamicSharedMemorySize, GEMM_SMEM);
    qkv_mma_kernel<<<dim3(Hh / BNt, M_TOT / BMt, 3), 256, GEMM_SMEM>>>();

    // 2) Tensor-core flash attention (single-pass fp16, KVT=128)
    cudaFuncSetAttribute(attn_mma_kernel, cudaFuncAttributeMaxDynamicSharedMemorySize, ATTN_SMEM);
    attn_mma_kernel<<<dim3(Nn / QT, Bb * NH), 256, ATTN_SMEM>>>();

    // 3) Output projection (fp16 1-pass HMMA)
    cudaFuncSetAttribute(proj_mma_kernel, cudaFuncAttributeMaxDynamicSharedMemorySize, GEMM_SMEM);
    proj_mma_kernel<<<dim3(Hh / BNt, M_TOT / BMt), 256, GEMM_SMEM>>>(bout, out);
}